// round 8
// baseline (speedup 1.0000x reference)
#include <cuda_runtime.h>
#include <math.h>

#define N_NODES 20000
#define N_EDGES 160000
#define OUT_PER_NODE 36

typedef unsigned long long u64;

// ---------------- packed f32x2 helpers (sm_103a FFMA2 path) ----------------
__device__ __forceinline__ u64 pack2(float a, float b) {
    u64 r; asm("mov.b64 %0, {%1,%2};" : "=l"(r) : "f"(a), "f"(b)); return r;
}
__device__ __forceinline__ void unpack2(u64 v, float& a, float& b) {
    asm("mov.b64 {%0,%1}, %2;" : "=f"(a), "=f"(b) : "l"(v));
}
__device__ __forceinline__ void ffma2(u64& d, u64 a, u64 b) {
    asm("fma.rn.f32x2 %0, %1, %2, %0;" : "+l"(d) : "l"(a), "l"(b));
}
__device__ __forceinline__ float silu_f(float x) {
    return __fdividef(x, 1.0f + __expf(-x));
}

// ---------------- scratch ----------------
__device__ float d_Ai[N_NODES * 8];
__device__ float d_g3[N_EDGES * 64];        // row-major per CSR slot: [i][c]
__device__ u64   d_Mp[3 * 8192];            // [l][(u*8+v)*128 + c*2 + wp] = (w0,w1)/(w2,w3) pair
__device__ int   d_deg[N_NODES];
__device__ int   d_rowptr[N_NODES + 1];
__device__ int   d_fill[N_NODES];
__device__ int   d_csr[N_EDGES];

// ---------------- kernel 1: zero degree counters ----------------
__global__ void k_zero() {
    int i = blockIdx.x * blockDim.x + threadIdx.x;
    if (i < N_NODES) d_deg[i] = 0;
}

// ---------------- kernel 2: fused node MLP + M permute + degree count ----------------
// blocks [0,79): node MLP; [79,175): permute; [175,800): degree count
#define NODE_BLOCKS 79
#define PERM_BLOCKS 96
__global__ __launch_bounds__(256) void k_prepcount(
    const float* __restrict__ emb_table,
    const float* __restrict__ w1, const float* __restrict__ b1,
    const float* __restrict__ w2, const float* __restrict__ b2,
    const float* __restrict__ w3, const float* __restrict__ b3,
    const int* __restrict__ A,
    const float* __restrict__ fc_w4,
    const int* __restrict__ edge_dst)
{
    int tid = threadIdx.x;
    int bx = blockIdx.x;
    if (bx >= NODE_BLOCKS + PERM_BLOCKS) {
        int e = (bx - NODE_BLOCKS - PERM_BLOCKS) * 256 + tid;
        if (e < N_EDGES) atomicAdd(&d_deg[edge_dst[e]], 1);
        return;
    }
    if (bx >= NODE_BLOCKS) {
        // permute fc_w4 [c(64)][l(3)][u(8)][v(8)][w(4)] into w-paired layout
        int idx = (bx - NODE_BLOCKS) * 256 + tid;      // < 24576
        int l = idx / 8192;
        int r = idx - l * 8192;
        int uv = r >> 7;
        int q  = r & 127;
        int c  = q >> 1;
        int wp = q & 1;
        int u  = uv >> 3;
        int v  = uv & 7;
        const float* p = fc_w4 + c * 768 + l * 256 + u * 32 + v * 4 + wp * 2;
        d_Mp[idx] = pack2(p[0], p[1]);
        return;
    }

    __shared__ __align__(16) float s_w1[16 * 64];
    __shared__ __align__(16) float s_w2[64 * 32];
    __shared__ __align__(16) float s_w3[32 * 8];
    __shared__ float s_b1[64];
    __shared__ float s_b2[32];
    __shared__ float s_b3[8];
    for (int i = tid; i < 16 * 64; i += 256) s_w1[i] = w1[i];
    for (int i = tid; i < 64 * 32; i += 256) s_w2[i] = w2[i];
    for (int i = tid; i < 32 * 8;  i += 256) s_w3[i] = w3[i];
    if (tid < 64) s_b1[tid] = b1[tid];
    if (tid < 32) s_b2[tid] = b2[tid];
    if (tid < 8)  s_b3[tid] = b3[tid];
    __syncthreads();

    int n = bx * 256 + tid;
    if (n >= N_NODES) return;

    int a = A[n];
    float e[16];
    #pragma unroll
    for (int i = 0; i < 16; i++) e[i] = emb_table[a * 16 + i];

    float h1[64];
    #pragma unroll
    for (int j = 0; j < 64; j++) h1[j] = s_b1[j];
    #pragma unroll
    for (int i = 0; i < 16; i++) {
        float ei = e[i];
        #pragma unroll
        for (int j = 0; j < 64; j++) h1[j] += ei * s_w1[i * 64 + j];
    }
    #pragma unroll
    for (int j = 0; j < 64; j++) h1[j] = silu_f(h1[j]);

    float h2[32];
    #pragma unroll
    for (int j = 0; j < 32; j++) h2[j] = s_b2[j];
    #pragma unroll
    for (int i = 0; i < 64; i++) {
        float hi = h1[i];
        #pragma unroll
        for (int j = 0; j < 32; j++) h2[j] += hi * s_w2[i * 32 + j];
    }
    #pragma unroll
    for (int j = 0; j < 32; j++) h2[j] = silu_f(h2[j]);

    float ai[8];
    #pragma unroll
    for (int j = 0; j < 8; j++) ai[j] = s_b3[j];
    #pragma unroll
    for (int i = 0; i < 32; i++) {
        float hi = h2[i];
        #pragma unroll
        for (int j = 0; j < 8; j++) ai[j] += hi * s_w3[i * 8 + j];
    }
    #pragma unroll
    for (int j = 0; j < 8; j++) d_Ai[n * 8 + j] = ai[j];
}

// ---------------- kernel 3: single-block prefix scan -> rowptr + fill ----------------
__global__ __launch_bounds__(1024) void k_scan() {
    __shared__ int sbuf[1024];
    int tid = threadIdx.x;
    int carry = 0;
    if (tid == 0) d_rowptr[0] = 0;
    for (int base = 0; base < N_NODES; base += 1024) {
        int i = base + tid;
        int v = (i < N_NODES) ? d_deg[i] : 0;
        sbuf[tid] = v;
        __syncthreads();
        for (int off = 1; off < 1024; off <<= 1) {
            int t = (tid >= off) ? sbuf[tid - off] : 0;
            __syncthreads();
            sbuf[tid] += t;
            __syncthreads();
        }
        if (i < N_NODES) d_rowptr[i + 1] = carry + sbuf[tid];
        int tot = sbuf[1023];
        __syncthreads();
        carry += tot;
    }
    __syncthreads();
    for (int i = tid; i < N_NODES; i += 1024) d_fill[i] = d_rowptr[i];
}

// ---------------- kernel 4: scatter edges into CSR ----------------
__global__ void k_scatter(const int* __restrict__ edge_dst) {
    int e = blockIdx.x * 256 + threadIdx.x;
    if (e < N_EDGES) {
        int p = atomicAdd(&d_fill[edge_dst[e]], 1);
        d_csr[p] = e;
    }
}

// ---------------- geometry helper ----------------
__device__ __forceinline__ void edge_geom(
    const float* __restrict__ pos, const int* __restrict__ batch,
    const float* __restrict__ shifts, const float* __restrict__ cell,
    int e, int s, int d, float& ex, float& ey, float& ez, float& r)
{
    float sx = shifts[e * 3 + 0], sy = shifts[e * 3 + 1], sz = shifts[e * 3 + 2];
    int b = batch[s];
    const float* C = cell + b * 9;
    float shx = sx * C[0] + sy * C[3] + sz * C[6];
    float shy = sx * C[1] + sy * C[4] + sz * C[7];
    float shz = sx * C[2] + sy * C[5] + sz * C[8];
    ex = pos[d * 3 + 0] - pos[s * 3 + 0] + shx;
    ey = pos[d * 3 + 1] - pos[s * 3 + 1] + shy;
    ez = pos[d * 3 + 2] - pos[s * 3 + 2] + shz;
    r = sqrtf(ex * ex + ey * ey + ez * ez);
}

// ---------------- kernel 5: radial chain over CSR slots -> g3 rows ----------------
__global__ __launch_bounds__(128, 3) void k_radial(
    const float* __restrict__ pos, const int* __restrict__ batch,
    const int* __restrict__ src, const int* __restrict__ dst,
    const float* __restrict__ shifts, const float* __restrict__ cell,
    const float* __restrict__ fw1, const float* __restrict__ fw2,
    const float* __restrict__ fw3)
{
    __shared__ __align__(16) float s_w1[16 * 64];
    __shared__ __align__(16) float s_w2[64 * 64];
    __shared__ __align__(16) float s_w3[64 * 64];
    int tid = threadIdx.x;
    for (int i = tid; i < 16 * 64; i += 128) s_w1[i] = fw1[i];
    for (int i = tid; i < 64 * 64; i += 128) s_w2[i] = fw2[i];
    for (int i = tid; i < 64 * 64; i += 128) s_w3[i] = fw3[i];
    __syncthreads();

    int i = blockIdx.x * 128 + tid;        // CSR slot (exact cover)
    int e = d_csr[i];

    int s = src[e], d = dst[e];
    float ex, ey, ez, r;
    edge_geom(pos, batch, shifts, cell, e, s, d, ex, ey, ez, r);

    const float step = 5.0f / 17.0f;
    const float inv_step = 17.0f / 5.0f;
    const float rb_scale = 4.0f / 1.12f;

    float rb[16];
    #pragma unroll
    for (int j = 0; j < 16; j++) {
        float c = step * (float)(j + 1);
        float t = (r - c) * inv_step;
        rb[j] = __expf(-t * t) * rb_scale;
    }

    float g1[64];
    #pragma unroll
    for (int h = 0; h < 2; h++) {
        u64 acc[16];
        #pragma unroll
        for (int p = 0; p < 16; p++) acc[p] = 0ULL;
        #pragma unroll 4
        for (int j = 0; j < 16; j++) {
            u64 rr = pack2(rb[j], rb[j]);
            const ulonglong2* row = (const ulonglong2*)&s_w1[j * 64 + h * 32];
            #pragma unroll
            for (int k = 0; k < 8; k++) {
                ulonglong2 m = row[k];
                ffma2(acc[2 * k + 0], rr, m.x);
                ffma2(acc[2 * k + 1], rr, m.y);
            }
        }
        #pragma unroll
        for (int p = 0; p < 16; p++) {
            float a, b; unpack2(acc[p], a, b);
            g1[h * 32 + 2 * p + 0] = silu_f(a * 0.25f);
            g1[h * 32 + 2 * p + 1] = silu_f(b * 0.25f);
        }
    }

    float g2[64];
    #pragma unroll
    for (int q = 0; q < 4; q++) {
        u64 acc[8];
        #pragma unroll
        for (int p = 0; p < 8; p++) acc[p] = 0ULL;
        #pragma unroll 4
        for (int j = 0; j < 64; j++) {
            u64 gi = pack2(g1[j], g1[j]);
            const ulonglong2* row = (const ulonglong2*)&s_w2[j * 64 + q * 16];
            #pragma unroll
            for (int k = 0; k < 4; k++) {
                ulonglong2 m = row[k];
                ffma2(acc[2 * k + 0], gi, m.x);
                ffma2(acc[2 * k + 1], gi, m.y);
            }
        }
        #pragma unroll
        for (int p = 0; p < 8; p++) {
            float a, b; unpack2(acc[p], a, b);
            g2[q * 16 + 2 * p + 0] = silu_f(a * 0.125f);
            g2[q * 16 + 2 * p + 1] = silu_f(b * 0.125f);
        }
    }

    #pragma unroll
    for (int q = 0; q < 4; q++) {
        u64 acc[8];
        #pragma unroll
        for (int p = 0; p < 8; p++) acc[p] = 0ULL;
        #pragma unroll 4
        for (int j = 0; j < 64; j++) {
            u64 gi = pack2(g2[j], g2[j]);
            const ulonglong2* row = (const ulonglong2*)&s_w3[j * 64 + q * 16];
            #pragma unroll
            for (int k = 0; k < 4; k++) {
                ulonglong2 m = row[k];
                ffma2(acc[2 * k + 0], gi, m.x);
                ffma2(acc[2 * k + 1], gi, m.y);
            }
        }
        #pragma unroll
        for (int p = 0; p < 8; p++) {
            float a, b; unpack2(acc[p], a, b);
            float2 o = make_float2(silu_f(a * 0.125f), silu_f(b * 0.125f));
            *(float2*)&d_g3[i * 64 + q * 16 + 2 * p] = o;
        }
    }
}

// ---------------- kernel 6: dst-factorized contraction, warp-per-node ----------------
__global__ __launch_bounds__(256, 2) void k_main(
    const float* __restrict__ pos, const int* __restrict__ batch,
    const int* __restrict__ src,
    const float* __restrict__ shifts, const float* __restrict__ cell,
    float* __restrict__ out)
{
    extern __shared__ __align__(16) u64 sM2[];   // 8192 u64 = 64 KB (l slice)
    const int l = blockIdx.y;
    for (int i = threadIdx.x; i < 8192; i += 256) sM2[i] = d_Mp[l * 8192 + i];
    __syncthreads();

    const int wid = threadIdx.x >> 5;
    const int lane = threadIdx.x & 31;
    const float4* Ai4 = (const float4*)d_Ai;
    const u64 ONE2 = pack2(1.0f, 1.0f);

    // per-lane output-component mapping
    int wsel, ksel, ncomp, obase;
    if (l == 0)      { wsel = lane;      ksel = 0;              ncomp = 4;  obase = 0;  }
    else if (l == 1) { wsel = lane / 3;  ksel = lane - wsel * 3; ncomp = 12; obase = 4;  }
    else             { wsel = lane / 5;  ksel = lane - wsel * 5; ncomp = 20; obase = 16; }

    for (int n = blockIdx.x * 8 + wid; n < N_NODES; n += gridDim.x * 8) {
        int beg = d_rowptr[n];
        int end = d_rowptr[n + 1];
        float acc = 0.0f;

        if (end > beg) {
            float4 b0 = Ai4[n * 2], b1 = Ai4[n * 2 + 1];
            float Ad[8] = {b0.x, b0.y, b0.z, b0.w, b1.x, b1.y, b1.z, b1.w};

            // ---- build M''[c,u,wpair] distributed: lane owns c=lane and c=lane+32 ----
            u64 M2[32];
            #pragma unroll
            for (int p = 0; p < 32; p++) M2[p] = 0ULL;
            #pragma unroll
            for (int c2 = 0; c2 < 2; c2++) {
                int c = c2 * 32 + lane;
                #pragma unroll
                for (int v = 0; v < 8; v++) {
                    u64 adv = pack2(Ad[v], Ad[v]);
                    #pragma unroll
                    for (int u = 0; u < 8; u++) {
                        ulonglong2 mm =
                            *(const ulonglong2*)&sM2[(u * 8 + v) * 128 + c * 2];
                        ffma2(M2[c2 * 16 + u * 2 + 0], adv, mm.x);
                        ffma2(M2[c2 * 16 + u * 2 + 1], adv, mm.y);
                    }
                }
            }

            // ---- edge phase ----
            for (int i = beg; i < end; i++) {
                int e = d_csr[i];
                int s = src[e];
                float4 a0 = Ai4[s * 2], a1 = Ai4[s * 2 + 1];
                float As[8] = {a0.x, a0.y, a0.z, a0.w, a1.x, a1.y, a1.z, a1.w};
                float g0 = d_g3[i * 64 + lane];
                float g1 = d_g3[i * 64 + 32 + lane];
                u64 gg0 = pack2(g0, g0);
                u64 gg1 = pack2(g1, g1);

                u64 S0 = 0ULL, S1 = 0ULL;
                #pragma unroll
                for (int u = 0; u < 8; u++) {
                    u64 asu = pack2(As[u], As[u]);
                    u64 f0 = 0ULL; ffma2(f0, gg0, asu);
                    ffma2(S0, f0, M2[u * 2 + 0]);
                    ffma2(S1, f0, M2[u * 2 + 1]);
                    u64 f1 = 0ULL; ffma2(f1, gg1, asu);
                    ffma2(S0, f1, M2[16 + u * 2 + 0]);
                    ffma2(S1, f1, M2[16 + u * 2 + 1]);
                }

                // butterfly reduce over 32 lanes (adds via ffma2 with 1.0)
                #pragma unroll
                for (int off = 16; off; off >>= 1) {
                    u64 t0 = __shfl_xor_sync(0xffffffffu, S0, off);
                    u64 t1 = __shfl_xor_sync(0xffffffffu, S1, off);
                    ffma2(S0, t0, ONE2);
                    ffma2(S1, t1, ONE2);
                }

                float W[4];
                unpack2(S0, W[0], W[1]);
                unpack2(S1, W[2], W[3]);
                float Wv = (wsel == 0) ? W[0] : (wsel == 1) ? W[1]
                          : (wsel == 2) ? W[2] : W[3];

                if (l == 0) {
                    acc += Wv;
                } else {
                    float ex, ey, ez, r;
                    edge_geom(pos, batch, shifts, cell, e, s, n, ex, ey, ez, r);
                    float inv_r = __fdividef(1.0f, fmaxf(r, 1e-9f));
                    float x = ex * inv_r, y = ey * inv_r, z = ez * inv_r;
                    float sh;
                    if (l == 1) {
                        const float s3 = 1.7320508075688772f;
                        sh = (ksel == 0) ? s3 * y : (ksel == 1) ? s3 * z : s3 * x;
                    } else {
                        const float s15 = 3.872983346207417f;
                        const float s5 = 2.23606797749979f;
                        sh = (ksel == 0) ? s15 * x * y
                           : (ksel == 1) ? s15 * y * z
                           : (ksel == 2) ? 0.5f * s5 * (3.0f * z * z - 1.0f)
                           : (ksel == 3) ? s15 * x * z
                                         : 0.5f * s15 * (x * x - y * y);
                    }
                    acc += Wv * sh;
                }
            }
        }

        int deg = end - beg;
        float sc = (1.0f / 64.0f) / (float)(deg > 0 ? deg : 1);
        if (lane < ncomp) out[n * OUT_PER_NODE + obase + lane] = acc * sc;
    }
}

// ---------------- launch ----------------
extern "C" void kernel_launch(void* const* d_in, const int* in_sizes, int n_in,
                              void* d_out, int out_size) {
    const float* pos      = (const float*)d_in[0];
    const int*   A        = (const int*)d_in[1];
    const int*   batch    = (const int*)d_in[2];
    const int*   edge_src = (const int*)d_in[3];
    const int*   edge_dst = (const int*)d_in[4];
    const float* shifts   = (const float*)d_in[5];
    const float* cell     = (const float*)d_in[6];
    const float* emb      = (const float*)d_in[7];
    const float* fit_w1   = (const float*)d_in[8];
    const float* fit_b1   = (const float*)d_in[9];
    const float* fit_w2   = (const float*)d_in[10];
    const float* fit_b2   = (const float*)d_in[11];
    const float* fit_w3   = (const float*)d_in[12];
    const float* fit_b3   = (const float*)d_in[13];
    const float* fc_w1    = (const float*)d_in[14];
    const float* fc_w2    = (const float*)d_in[15];
    const float* fc_w3    = (const float*)d_in[16];
    const float* fc_w4    = (const float*)d_in[17];
    float* out = (float*)d_out;

    cudaFuncSetAttribute(k_main, cudaFuncAttributeMaxDynamicSharedMemorySize,
                         8192 * (int)sizeof(u64));

    k_zero<<<(N_NODES + 255) / 256, 256>>>();
    k_prepcount<<<NODE_BLOCKS + PERM_BLOCKS + (N_EDGES / 256), 256>>>(
        emb, fit_w1, fit_b1, fit_w2, fit_b2, fit_w3, fit_b3, A, fc_w4, edge_dst);
    k_scan<<<1, 1024>>>();
    k_scatter<<<N_EDGES / 256, 256>>>(edge_dst);
    k_radial<<<N_EDGES / 128, 128>>>(pos, batch, edge_src, edge_dst,
                                     shifts, cell, fc_w1, fc_w2, fc_w3);
    dim3 mg(625, 3);
    k_main<<<mg, 256, 8192 * sizeof(u64)>>>(pos, batch, edge_src,
                                            shifts, cell, out);
}

// round 9
// speedup vs baseline: 1.2615x; 1.2615x over previous
#include <cuda_runtime.h>
#include <math.h>

#define N_NODES 20000
#define N_EDGES 160000
#define OUT_PER_NODE 36

typedef unsigned long long u64;

// ---------------- packed f32x2 helpers ----------------
__device__ __forceinline__ u64 pack2(float a, float b) {
    u64 r; asm("mov.b64 %0, {%1,%2};" : "=l"(r) : "f"(a), "f"(b)); return r;
}
__device__ __forceinline__ void unpack2(u64 v, float& a, float& b) {
    asm("mov.b64 {%0,%1}, %2;" : "=f"(a), "=f"(b) : "l"(v));
}
__device__ __forceinline__ void ffma2(u64& d, u64 a, u64 b) {
    asm("fma.rn.f32x2 %0, %1, %2, %0;" : "+l"(d) : "l"(a), "l"(b));
}
__device__ __forceinline__ float silu_f(float x) {
    return __fdividef(x, 1.0f + __expf(-x));
}

// ---------------- scratch ----------------
__device__ float d_Ai[N_NODES * 8];
__device__ u64   d_Aip[N_NODES * 4];        // (Ai[2j],Ai[2j+1]) pairs
__device__ float d_g3[N_EDGES * 64];        // [slot][c]
__device__ float d_sh[N_EDGES * 8];         // [slot][sh1_0..2, sh2_0..4]
__device__ float d_Ml[3 * 512 * 32];        // [l][cu][v*4+w]
__device__ int   d_deg[N_NODES];
__device__ int   d_rowptr[N_NODES + 1];
__device__ int   d_fill[N_NODES];
__device__ int   d_csr[N_EDGES];

// ---------------- kernel 1: zero degree counters ----------------
__global__ void k_zero() {
    int i = blockIdx.x * blockDim.x + threadIdx.x;
    if (i < N_NODES) d_deg[i] = 0;
}

// ---------------- kernel 2: node MLP + M permute + degree count ----------------
#define NODE_BLOCKS 79
#define PERM_BLOCKS 192
__global__ __launch_bounds__(256) void k_prepcount(
    const float* __restrict__ emb_table,
    const float* __restrict__ w1, const float* __restrict__ b1,
    const float* __restrict__ w2, const float* __restrict__ b2,
    const float* __restrict__ w3, const float* __restrict__ b3,
    const int* __restrict__ A,
    const float* __restrict__ fc_w4,
    const int* __restrict__ edge_dst)
{
    int tid = threadIdx.x;
    int bx = blockIdx.x;
    if (bx >= NODE_BLOCKS + PERM_BLOCKS) {
        int e = (bx - NODE_BLOCKS - PERM_BLOCKS) * 256 + tid;
        if (e < N_EDGES) atomicAdd(&d_deg[edge_dst[e]], 1);
        return;
    }
    if (bx >= NODE_BLOCKS) {
        // fc_w4 [c][l][u][v][w] -> d_Ml[l][(c*8+u)][v*4+w]
        int idx = (bx - NODE_BLOCKS) * 256 + tid;   // < 49152
        int c = idx / 768;
        int rem = idx - c * 768;
        int l = rem / 256;
        int rem2 = rem - l * 256;
        int u = rem2 / 32;
        int vw = rem2 - u * 32;
        d_Ml[l * (512 * 32) + (c * 8 + u) * 32 + vw] = fc_w4[idx];
        return;
    }

    __shared__ __align__(16) float s_w1[16 * 64];
    __shared__ __align__(16) float s_w2[64 * 32];
    __shared__ __align__(16) float s_w3[32 * 8];
    __shared__ float s_b1[64];
    __shared__ float s_b2[32];
    __shared__ float s_b3[8];
    for (int i = tid; i < 16 * 64; i += 256) s_w1[i] = w1[i];
    for (int i = tid; i < 64 * 32; i += 256) s_w2[i] = w2[i];
    for (int i = tid; i < 32 * 8;  i += 256) s_w3[i] = w3[i];
    if (tid < 64) s_b1[tid] = b1[tid];
    if (tid < 32) s_b2[tid] = b2[tid];
    if (tid < 8)  s_b3[tid] = b3[tid];
    __syncthreads();

    int n = bx * 256 + tid;
    if (n >= N_NODES) return;

    int a = A[n];
    float e[16];
    #pragma unroll
    for (int i = 0; i < 16; i++) e[i] = emb_table[a * 16 + i];

    float h1[64];
    #pragma unroll
    for (int j = 0; j < 64; j++) h1[j] = s_b1[j];
    #pragma unroll
    for (int i = 0; i < 16; i++) {
        float ei = e[i];
        #pragma unroll
        for (int j = 0; j < 64; j++) h1[j] += ei * s_w1[i * 64 + j];
    }
    #pragma unroll
    for (int j = 0; j < 64; j++) h1[j] = silu_f(h1[j]);

    float h2[32];
    #pragma unroll
    for (int j = 0; j < 32; j++) h2[j] = s_b2[j];
    #pragma unroll
    for (int i = 0; i < 64; i++) {
        float hi = h1[i];
        #pragma unroll
        for (int j = 0; j < 32; j++) h2[j] += hi * s_w2[i * 32 + j];
    }
    #pragma unroll
    for (int j = 0; j < 32; j++) h2[j] = silu_f(h2[j]);

    float ai[8];
    #pragma unroll
    for (int j = 0; j < 8; j++) ai[j] = s_b3[j];
    #pragma unroll
    for (int i = 0; i < 32; i++) {
        float hi = h2[i];
        #pragma unroll
        for (int j = 0; j < 8; j++) ai[j] += hi * s_w3[i * 8 + j];
    }
    #pragma unroll
    for (int j = 0; j < 8; j++) d_Ai[n * 8 + j] = ai[j];
    #pragma unroll
    for (int j = 0; j < 4; j++) d_Aip[n * 4 + j] = pack2(ai[2 * j], ai[2 * j + 1]);
}

// ---------------- kernel 3: single-block prefix scan ----------------
__global__ __launch_bounds__(1024) void k_scan() {
    __shared__ int sbuf[1024];
    int tid = threadIdx.x;
    int carry = 0;
    if (tid == 0) d_rowptr[0] = 0;
    for (int base = 0; base < N_NODES; base += 1024) {
        int i = base + tid;
        int v = (i < N_NODES) ? d_deg[i] : 0;
        sbuf[tid] = v;
        __syncthreads();
        for (int off = 1; off < 1024; off <<= 1) {
            int t = (tid >= off) ? sbuf[tid - off] : 0;
            __syncthreads();
            sbuf[tid] += t;
            __syncthreads();
        }
        if (i < N_NODES) d_rowptr[i + 1] = carry + sbuf[tid];
        int tot = sbuf[1023];
        __syncthreads();
        carry += tot;
    }
    __syncthreads();
    for (int i = tid; i < N_NODES; i += 1024) d_fill[i] = d_rowptr[i];
}

// ---------------- kernel 4: scatter edges into CSR ----------------
__global__ void k_scatter(const int* __restrict__ edge_dst) {
    int e = blockIdx.x * 256 + threadIdx.x;
    if (e < N_EDGES) {
        int p = atomicAdd(&d_fill[edge_dst[e]], 1);
        d_csr[p] = e;
    }
}

// ---------------- geometry helper ----------------
__device__ __forceinline__ void edge_geom(
    const float* __restrict__ pos, const int* __restrict__ batch,
    const float* __restrict__ shifts, const float* __restrict__ cell,
    int e, int s, int d, float& ex, float& ey, float& ez, float& r)
{
    float sx = shifts[e * 3 + 0], sy = shifts[e * 3 + 1], sz = shifts[e * 3 + 2];
    int b = batch[s];
    const float* C = cell + b * 9;
    float shx = sx * C[0] + sy * C[3] + sz * C[6];
    float shy = sx * C[1] + sy * C[4] + sz * C[7];
    float shz = sx * C[2] + sy * C[5] + sz * C[8];
    ex = pos[d * 3 + 0] - pos[s * 3 + 0] + shx;
    ey = pos[d * 3 + 1] - pos[s * 3 + 1] + shy;
    ez = pos[d * 3 + 2] - pos[s * 3 + 2] + shz;
    r = sqrtf(ex * ex + ey * ey + ez * ez);
}

// ---------------- kernel 5: radial chain + sh per CSR slot ----------------
__global__ __launch_bounds__(128, 3) void k_radial(
    const float* __restrict__ pos, const int* __restrict__ batch,
    const int* __restrict__ src, const int* __restrict__ dst,
    const float* __restrict__ shifts, const float* __restrict__ cell,
    const float* __restrict__ fw1, const float* __restrict__ fw2,
    const float* __restrict__ fw3)
{
    __shared__ __align__(16) float s_w1[16 * 64];
    __shared__ __align__(16) float s_w2[64 * 64];
    __shared__ __align__(16) float s_w3[64 * 64];
    int tid = threadIdx.x;
    for (int i = tid; i < 16 * 64; i += 128) s_w1[i] = fw1[i];
    for (int i = tid; i < 64 * 64; i += 128) s_w2[i] = fw2[i];
    for (int i = tid; i < 64 * 64; i += 128) s_w3[i] = fw3[i];
    __syncthreads();

    int i = blockIdx.x * 128 + tid;        // CSR slot
    int e = d_csr[i];

    int s = src[e], d = dst[e];
    float ex, ey, ez, r;
    edge_geom(pos, batch, shifts, cell, e, s, d, ex, ey, ez, r);

    // spherical harmonics per slot
    {
        float inv_r = __fdividef(1.0f, fmaxf(r, 1e-9f));
        float x = ex * inv_r, y = ey * inv_r, z = ez * inv_r;
        const float s3 = 1.7320508075688772f;
        const float s15 = 3.872983346207417f;
        const float s5 = 2.23606797749979f;
        float4 o0 = make_float4(s3 * y, s3 * z, s3 * x, s15 * x * y);
        float4 o1 = make_float4(s15 * y * z, 0.5f * s5 * (3.0f * z * z - 1.0f),
                                s15 * x * z, 0.5f * s15 * (x * x - y * y));
        *(float4*)&d_sh[i * 8 + 0] = o0;
        *(float4*)&d_sh[i * 8 + 4] = o1;
    }

    const float step = 5.0f / 17.0f;
    const float inv_step = 17.0f / 5.0f;
    const float rb_scale = 4.0f / 1.12f;

    float rb[16];
    #pragma unroll
    for (int j = 0; j < 16; j++) {
        float c = step * (float)(j + 1);
        float t = (r - c) * inv_step;
        rb[j] = __expf(-t * t) * rb_scale;
    }

    float g1[64];
    #pragma unroll
    for (int h = 0; h < 2; h++) {
        u64 acc[16];
        #pragma unroll
        for (int p = 0; p < 16; p++) acc[p] = 0ULL;
        #pragma unroll 4
        for (int j = 0; j < 16; j++) {
            u64 rr = pack2(rb[j], rb[j]);
            const ulonglong2* row = (const ulonglong2*)&s_w1[j * 64 + h * 32];
            #pragma unroll
            for (int k = 0; k < 8; k++) {
                ulonglong2 m = row[k];
                ffma2(acc[2 * k + 0], rr, m.x);
                ffma2(acc[2 * k + 1], rr, m.y);
            }
        }
        #pragma unroll
        for (int p = 0; p < 16; p++) {
            float a, b; unpack2(acc[p], a, b);
            g1[h * 32 + 2 * p + 0] = silu_f(a * 0.25f);
            g1[h * 32 + 2 * p + 1] = silu_f(b * 0.25f);
        }
    }

    float g2[64];
    #pragma unroll
    for (int q = 0; q < 4; q++) {
        u64 acc[8];
        #pragma unroll
        for (int p = 0; p < 8; p++) acc[p] = 0ULL;
        #pragma unroll 4
        for (int j = 0; j < 64; j++) {
            u64 gi = pack2(g1[j], g1[j]);
            const ulonglong2* row = (const ulonglong2*)&s_w2[j * 64 + q * 16];
            #pragma unroll
            for (int k = 0; k < 4; k++) {
                ulonglong2 m = row[k];
                ffma2(acc[2 * k + 0], gi, m.x);
                ffma2(acc[2 * k + 1], gi, m.y);
            }
        }
        #pragma unroll
        for (int p = 0; p < 8; p++) {
            float a, b; unpack2(acc[p], a, b);
            g2[q * 16 + 2 * p + 0] = silu_f(a * 0.125f);
            g2[q * 16 + 2 * p + 1] = silu_f(b * 0.125f);
        }
    }

    #pragma unroll
    for (int q = 0; q < 4; q++) {
        u64 acc[8];
        #pragma unroll
        for (int p = 0; p < 8; p++) acc[p] = 0ULL;
        #pragma unroll 4
        for (int j = 0; j < 64; j++) {
            u64 gi = pack2(g2[j], g2[j]);
            const ulonglong2* row = (const ulonglong2*)&s_w3[j * 64 + q * 16];
            #pragma unroll
            for (int k = 0; k < 4; k++) {
                ulonglong2 m = row[k];
                ffma2(acc[2 * k + 0], gi, m.x);
                ffma2(acc[2 * k + 1], gi, m.y);
            }
        }
        #pragma unroll
        for (int p = 0; p < 8; p++) {
            float a, b; unpack2(acc[p], a, b);
            float2 o = make_float2(silu_f(a * 0.125f), silu_f(b * 0.125f));
            *(float2*)&d_g3[i * 64 + q * 16 + 2 * p] = o;
        }
    }
}

// ---------------- kernel 6: factorized contraction, warp-per-node, per-l ----------------
// lane owns cu in [16*lane, 16*lane+16): c = 2*lane + (j>=4), u pairs via d_Aip.
// G[k][j] accumulates over edges; one butterfly per node.
template<int L>
__global__ __launch_bounds__(256) void k_main(
    const int* __restrict__ src, float* __restrict__ out)
{
    constexpr int K   = (L == 0) ? 1 : (L == 1) ? 3 : 5;
    constexpr int OFF = (L == 0) ? 0 : (L == 1) ? 4 : 16;
    extern __shared__ float sM[];   // 16384 floats, v-xor swizzled

    for (int idx = threadIdx.x; idx < 16384; idx += 256) {
        int cu = idx >> 5, vw = idx & 31;
        int v = vw >> 2, w = vw & 3;
        int pv = v ^ ((cu >> 4) & 7);
        sM[(cu << 5) + (pv << 2) + w] = d_Ml[L * 16384 + idx];
    }
    __syncthreads();

    const int wid = threadIdx.x >> 5;
    const int lane = threadIdx.x & 31;
    const u64 ONE2 = pack2(1.0f, 1.0f);

    for (int n = blockIdx.x * 8 + wid; n < N_NODES; n += gridDim.x * 8) {
        int beg = d_rowptr[n], end = d_rowptr[n + 1];
        int deg = end - beg;
        float* od = out + n * OUT_PER_NODE + OFF;
        if (deg == 0) {
            if (lane < 4 * K) od[lane] = 0.0f;
            continue;
        }

        // ---- B: accumulate G[k][j] over edges (lane-local, no shuffles) ----
        u64 G[K][8];
        #pragma unroll
        for (int k = 0; k < K; k++)
            #pragma unroll
            for (int j = 0; j < 8; j++) G[k][j] = 0ULL;

        for (int i = beg; i < end; i++) {
            int e = d_csr[i];
            int s = src[e];
            const ulonglong2* ap = (const ulonglong2*)&d_Aip[s * 4];
            ulonglong2 a01 = ap[0], a23 = ap[1];
            u64 aa[4] = {a01.x, a01.y, a23.x, a23.y};
            float2 gp = *(const float2*)&d_g3[i * 64 + 2 * lane];
            u64 g00 = pack2(gp.x, gp.x), g11 = pack2(gp.y, gp.y);
            u64 ff[8];
            #pragma unroll
            for (int j = 0; j < 4; j++) { ff[j] = 0ULL; ffma2(ff[j], g00, aa[j]); }
            #pragma unroll
            for (int j = 0; j < 4; j++) { ff[4 + j] = 0ULL; ffma2(ff[4 + j], g11, aa[j]); }
            if (L == 0) {
                #pragma unroll
                for (int j = 0; j < 8; j++) ffma2(G[0][j], ff[j], ONE2);
            } else {
                #pragma unroll
                for (int k = 0; k < K; k++) {
                    float shv = d_sh[i * 8 + ((L == 1) ? 0 : 3) + k];
                    u64 ss = pack2(shv, shv);
                    #pragma unroll
                    for (int j = 0; j < 8; j++) ffma2(G[k][j], ff[j], ss);
                }
            }
        }

        // ---- A: M''[cu] = sum_v Ad_v * M[cu][v][:] (lane's 16 cu) ----
        u64 AdP[8];
        {
            const float4* Ai4 = (const float4*)&d_Ai[n * 8];
            float4 b0 = Ai4[0], b1 = Ai4[1];
            AdP[0] = pack2(b0.x, b0.x); AdP[1] = pack2(b0.y, b0.y);
            AdP[2] = pack2(b0.z, b0.z); AdP[3] = pack2(b0.w, b0.w);
            AdP[4] = pack2(b1.x, b1.x); AdP[5] = pack2(b1.y, b1.y);
            AdP[6] = pack2(b1.z, b1.z); AdP[7] = pack2(b1.w, b1.w);
        }
        u64 M2[32];
        #pragma unroll
        for (int cu = 0; cu < 16; cu++) {
            u64 m0 = 0ULL, m1 = 0ULL;
            int base = (lane * 16 + cu) * 32;
            #pragma unroll
            for (int v = 0; v < 8; v++) {
                ulonglong2 mm =
                    *(const ulonglong2*)&sM[base + ((v ^ (lane & 7)) << 2)];
                ffma2(m0, AdP[v], mm.x);
                ffma2(m1, AdP[v], mm.y);
            }
            M2[cu * 2 + 0] = m0;
            M2[cu * 2 + 1] = m1;
        }

        // ---- C: out[k][wpair] = sum_cu G[k][cu] * M''[cu][wpair] ----
        u64 acc[K][2];
        #pragma unroll
        for (int k = 0; k < K; k++) { acc[k][0] = 0ULL; acc[k][1] = 0ULL; }
        #pragma unroll
        for (int j = 0; j < 8; j++) {
            u64 m00 = M2[4 * j + 0], m01 = M2[4 * j + 1];
            u64 m10 = M2[4 * j + 2], m11 = M2[4 * j + 3];
            #pragma unroll
            for (int k = 0; k < K; k++) {
                float ga, gb; unpack2(G[k][j], ga, gb);
                u64 gaa = pack2(ga, ga), gbb = pack2(gb, gb);
                ffma2(acc[k][0], gaa, m00);
                ffma2(acc[k][1], gaa, m01);
                ffma2(acc[k][0], gbb, m10);
                ffma2(acc[k][1], gbb, m11);
            }
        }

        // ---- butterfly reduce (once per node) ----
        #pragma unroll
        for (int off = 16; off; off >>= 1) {
            #pragma unroll
            for (int k = 0; k < K; k++) {
                u64 t0 = __shfl_xor_sync(0xffffffffu, acc[k][0], off);
                u64 t1 = __shfl_xor_sync(0xffffffffu, acc[k][1], off);
                ffma2(acc[k][0], t0, ONE2);
                ffma2(acc[k][1], t1, ONE2);
            }
        }

        if (lane == 0) {
            float sc = (1.0f / 64.0f) / (float)deg;
            #pragma unroll
            for (int k = 0; k < K; k++) {
                float W[4];
                unpack2(acc[k][0], W[0], W[1]);
                unpack2(acc[k][1], W[2], W[3]);
                #pragma unroll
                for (int w = 0; w < 4; w++) {
                    if (L == 0)      od[w] = W[w] * sc;
                    else if (L == 1) od[w * 3 + k] = W[w] * sc;
                    else             od[w * 5 + k] = W[w] * sc;
                }
            }
        }
    }
}

// ---------------- launch ----------------
extern "C" void kernel_launch(void* const* d_in, const int* in_sizes, int n_in,
                              void* d_out, int out_size) {
    const float* pos      = (const float*)d_in[0];
    const int*   A        = (const int*)d_in[1];
    const int*   batch    = (const int*)d_in[2];
    const int*   edge_src = (const int*)d_in[3];
    const int*   edge_dst = (const int*)d_in[4];
    const float* shifts   = (const float*)d_in[5];
    const float* cell     = (const float*)d_in[6];
    const float* emb      = (const float*)d_in[7];
    const float* fit_w1   = (const float*)d_in[8];
    const float* fit_b1   = (const float*)d_in[9];
    const float* fit_w2   = (const float*)d_in[10];
    const float* fit_b2   = (const float*)d_in[11];
    const float* fit_w3   = (const float*)d_in[12];
    const float* fit_b3   = (const float*)d_in[13];
    const float* fc_w1    = (const float*)d_in[14];
    const float* fc_w2    = (const float*)d_in[15];
    const float* fc_w3    = (const float*)d_in[16];
    const float* fc_w4    = (const float*)d_in[17];
    float* out = (float*)d_out;

    cudaFuncSetAttribute(k_main<0>, cudaFuncAttributeMaxDynamicSharedMemorySize, 65536);
    cudaFuncSetAttribute(k_main<1>, cudaFuncAttributeMaxDynamicSharedMemorySize, 65536);
    cudaFuncSetAttribute(k_main<2>, cudaFuncAttributeMaxDynamicSharedMemorySize, 65536);

    k_zero<<<(N_NODES + 255) / 256, 256>>>();
    k_prepcount<<<NODE_BLOCKS + PERM_BLOCKS + (N_EDGES / 256), 256>>>(
        emb, fit_w1, fit_b1, fit_w2, fit_b2, fit_w3, fit_b3, A, fc_w4, edge_dst);
    k_scan<<<1, 1024>>>();
    k_scatter<<<N_EDGES / 256, 256>>>(edge_dst);
    k_radial<<<N_EDGES / 128, 128>>>(pos, batch, edge_src, edge_dst,
                                     shifts, cell, fc_w1, fc_w2, fc_w3);
    k_main<0><<<296, 256, 65536>>>(edge_src, out);
    k_main<1><<<296, 256, 65536>>>(edge_src, out);
    k_main<2><<<296, 256, 65536>>>(edge_src, out);
}

// round 10
// speedup vs baseline: 1.3020x; 1.0321x over previous
#include <cuda_runtime.h>
#include <math.h>

#define N_NODES 20000
#define N_EDGES 160000
#define OUT_PER_NODE 36

typedef unsigned long long u64;

// ---------------- packed f32x2 helpers ----------------
__device__ __forceinline__ u64 pack2(float a, float b) {
    u64 r; asm("mov.b64 %0, {%1,%2};" : "=l"(r) : "f"(a), "f"(b)); return r;
}
__device__ __forceinline__ void unpack2(u64 v, float& a, float& b) {
    asm("mov.b64 {%0,%1}, %2;" : "=f"(a), "=f"(b) : "l"(v));
}
__device__ __forceinline__ void ffma2(u64& d, u64 a, u64 b) {
    asm("fma.rn.f32x2 %0, %1, %2, %0;" : "+l"(d) : "l"(a), "l"(b));
}
__device__ __forceinline__ float silu_f(float x) {
    return __fdividef(x, 1.0f + __expf(-x));
}

// ---------------- scratch ----------------
__device__ float d_Ai[N_NODES * 8];
__device__ u64   d_Aip[N_NODES * 4];        // (Ai[2j],Ai[2j+1]) pairs
__device__ float d_g3[N_EDGES * 64];        // [e][c]  (edge-indexed)
__device__ float d_sh[N_EDGES * 8];         // [e][sh1_0..2, sh2_0..4]
__device__ float d_Ml[3 * 512 * 32];        // [l][cu][v*4+w]
__device__ int   d_deg[N_NODES];
__device__ int   d_rowptr[N_NODES + 1];
__device__ int   d_fill[N_NODES];
__device__ int   d_csr[N_EDGES];

// ---------------- kernel 1: zero degree counters ----------------
__global__ void k_zero() {
    int i = blockIdx.x * blockDim.x + threadIdx.x;
    if (i < N_NODES) d_deg[i] = 0;
}

// ---------------- kernel 2: node MLP + M permute + degree count ----------------
#define NODE_BLOCKS 79
#define PERM_BLOCKS 192
__global__ __launch_bounds__(256) void k_prepcount(
    const float* __restrict__ emb_table,
    const float* __restrict__ w1, const float* __restrict__ b1,
    const float* __restrict__ w2, const float* __restrict__ b2,
    const float* __restrict__ w3, const float* __restrict__ b3,
    const int* __restrict__ A,
    const float* __restrict__ fc_w4,
    const int* __restrict__ edge_dst)
{
    int tid = threadIdx.x;
    int bx = blockIdx.x;
    if (bx >= NODE_BLOCKS + PERM_BLOCKS) {
        int e = (bx - NODE_BLOCKS - PERM_BLOCKS) * 256 + tid;
        if (e < N_EDGES) atomicAdd(&d_deg[edge_dst[e]], 1);
        return;
    }
    if (bx >= NODE_BLOCKS) {
        // fc_w4 [c][l][u][v][w] -> d_Ml[l][(c*8+u)][v*4+w]
        int idx = (bx - NODE_BLOCKS) * 256 + tid;   // < 49152
        int c = idx / 768;
        int rem = idx - c * 768;
        int l = rem / 256;
        int rem2 = rem - l * 256;
        int u = rem2 / 32;
        int vw = rem2 - u * 32;
        d_Ml[l * (512 * 32) + (c * 8 + u) * 32 + vw] = fc_w4[idx];
        return;
    }

    __shared__ __align__(16) float s_w1[16 * 64];
    __shared__ __align__(16) float s_w2[64 * 32];
    __shared__ __align__(16) float s_w3[32 * 8];
    __shared__ float s_b1[64];
    __shared__ float s_b2[32];
    __shared__ float s_b3[8];
    for (int i = tid; i < 16 * 64; i += 256) s_w1[i] = w1[i];
    for (int i = tid; i < 64 * 32; i += 256) s_w2[i] = w2[i];
    for (int i = tid; i < 32 * 8;  i += 256) s_w3[i] = w3[i];
    if (tid < 64) s_b1[tid] = b1[tid];
    if (tid < 32) s_b2[tid] = b2[tid];
    if (tid < 8)  s_b3[tid] = b3[tid];
    __syncthreads();

    int n = bx * 256 + tid;
    if (n >= N_NODES) return;

    int a = A[n];
    float e[16];
    #pragma unroll
    for (int i = 0; i < 16; i++) e[i] = emb_table[a * 16 + i];

    float h1[64];
    #pragma unroll
    for (int j = 0; j < 64; j++) h1[j] = s_b1[j];
    #pragma unroll
    for (int i = 0; i < 16; i++) {
        float ei = e[i];
        #pragma unroll
        for (int j = 0; j < 64; j++) h1[j] += ei * s_w1[i * 64 + j];
    }
    #pragma unroll
    for (int j = 0; j < 64; j++) h1[j] = silu_f(h1[j]);

    float h2[32];
    #pragma unroll
    for (int j = 0; j < 32; j++) h2[j] = s_b2[j];
    #pragma unroll
    for (int i = 0; i < 64; i++) {
        float hi = h1[i];
        #pragma unroll
        for (int j = 0; j < 32; j++) h2[j] += hi * s_w2[i * 32 + j];
    }
    #pragma unroll
    for (int j = 0; j < 32; j++) h2[j] = silu_f(h2[j]);

    float ai[8];
    #pragma unroll
    for (int j = 0; j < 8; j++) ai[j] = s_b3[j];
    #pragma unroll
    for (int i = 0; i < 32; i++) {
        float hi = h2[i];
        #pragma unroll
        for (int j = 0; j < 8; j++) ai[j] += hi * s_w3[i * 8 + j];
    }
    #pragma unroll
    for (int j = 0; j < 8; j++) d_Ai[n * 8 + j] = ai[j];
    #pragma unroll
    for (int j = 0; j < 4; j++) d_Aip[n * 4 + j] = pack2(ai[2 * j], ai[2 * j + 1]);
}

// ---------------- kernel 3: single-block prefix scan ----------------
__global__ __launch_bounds__(1024) void k_scan() {
    __shared__ int sbuf[1024];
    int tid = threadIdx.x;
    int carry = 0;
    if (tid == 0) d_rowptr[0] = 0;
    for (int base = 0; base < N_NODES; base += 1024) {
        int i = base + tid;
        int v = (i < N_NODES) ? d_deg[i] : 0;
        sbuf[tid] = v;
        __syncthreads();
        for (int off = 1; off < 1024; off <<= 1) {
            int t = (tid >= off) ? sbuf[tid - off] : 0;
            __syncthreads();
            sbuf[tid] += t;
            __syncthreads();
        }
        if (i < N_NODES) d_rowptr[i + 1] = carry + sbuf[tid];
        int tot = sbuf[1023];
        __syncthreads();
        carry += tot;
    }
    __syncthreads();
    for (int i = tid; i < N_NODES; i += 1024) d_fill[i] = d_rowptr[i];
}

// ---------------- geometry helper ----------------
__device__ __forceinline__ void edge_geom(
    const float* __restrict__ pos, const int* __restrict__ batch,
    const float* __restrict__ shifts, const float* __restrict__ cell,
    int e, int s, int d, float& ex, float& ey, float& ez, float& r)
{
    float sx = shifts[e * 3 + 0], sy = shifts[e * 3 + 1], sz = shifts[e * 3 + 2];
    int b = batch[s];
    const float* C = cell + b * 9;
    float shx = sx * C[0] + sy * C[3] + sz * C[6];
    float shy = sx * C[1] + sy * C[4] + sz * C[7];
    float shz = sx * C[2] + sy * C[5] + sz * C[8];
    ex = pos[d * 3 + 0] - pos[s * 3 + 0] + shx;
    ey = pos[d * 3 + 1] - pos[s * 3 + 1] + shy;
    ez = pos[d * 3 + 2] - pos[s * 3 + 2] + shz;
    r = sqrtf(ex * ex + ey * ey + ez * ez);
}

// ---------------- kernel 4 (launch slot 4): radial chain + sh, edge-indexed ----------------
__global__ __launch_bounds__(128, 3) void k_radial(
    const float* __restrict__ pos, const int* __restrict__ batch,
    const int* __restrict__ src, const int* __restrict__ dst,
    const float* __restrict__ shifts, const float* __restrict__ cell,
    const float* __restrict__ fw1, const float* __restrict__ fw2,
    const float* __restrict__ fw3)
{
    __shared__ __align__(16) float s_w1[16 * 64];
    __shared__ __align__(16) float s_w2[64 * 64];
    __shared__ __align__(16) float s_w3[64 * 64];
    int tid = threadIdx.x;
    for (int i = tid; i < 16 * 64; i += 128) s_w1[i] = fw1[i];
    for (int i = tid; i < 64 * 64; i += 128) s_w2[i] = fw2[i];
    for (int i = tid; i < 64 * 64; i += 128) s_w3[i] = fw3[i];
    __syncthreads();

    int e = blockIdx.x * 128 + tid;        // edge-indexed (no CSR dependency)

    int s = src[e], d = dst[e];
    float ex, ey, ez, r;
    edge_geom(pos, batch, shifts, cell, e, s, d, ex, ey, ez, r);

    // spherical harmonics
    {
        float inv_r = __fdividef(1.0f, fmaxf(r, 1e-9f));
        float x = ex * inv_r, y = ey * inv_r, z = ez * inv_r;
        const float s3 = 1.7320508075688772f;
        const float s15 = 3.872983346207417f;
        const float s5 = 2.23606797749979f;
        float4 o0 = make_float4(s3 * y, s3 * z, s3 * x, s15 * x * y);
        float4 o1 = make_float4(s15 * y * z, 0.5f * s5 * (3.0f * z * z - 1.0f),
                                s15 * x * z, 0.5f * s15 * (x * x - y * y));
        *(float4*)&d_sh[e * 8 + 0] = o0;
        *(float4*)&d_sh[e * 8 + 4] = o1;
    }

    const float step = 5.0f / 17.0f;
    const float inv_step = 17.0f / 5.0f;
    const float rb_scale = 4.0f / 1.12f;

    float rb[16];
    #pragma unroll
    for (int j = 0; j < 16; j++) {
        float c = step * (float)(j + 1);
        float t = (r - c) * inv_step;
        rb[j] = __expf(-t * t) * rb_scale;
    }

    float g1[64];
    #pragma unroll
    for (int h = 0; h < 2; h++) {
        u64 acc[16];
        #pragma unroll
        for (int p = 0; p < 16; p++) acc[p] = 0ULL;
        #pragma unroll 4
        for (int j = 0; j < 16; j++) {
            u64 rr = pack2(rb[j], rb[j]);
            const ulonglong2* row = (const ulonglong2*)&s_w1[j * 64 + h * 32];
            #pragma unroll
            for (int k = 0; k < 8; k++) {
                ulonglong2 m = row[k];
                ffma2(acc[2 * k + 0], rr, m.x);
                ffma2(acc[2 * k + 1], rr, m.y);
            }
        }
        #pragma unroll
        for (int p = 0; p < 16; p++) {
            float a, b; unpack2(acc[p], a, b);
            g1[h * 32 + 2 * p + 0] = silu_f(a * 0.25f);
            g1[h * 32 + 2 * p + 1] = silu_f(b * 0.25f);
        }
    }

    float g2[64];
    #pragma unroll
    for (int q = 0; q < 4; q++) {
        u64 acc[8];
        #pragma unroll
        for (int p = 0; p < 8; p++) acc[p] = 0ULL;
        #pragma unroll 4
        for (int j = 0; j < 64; j++) {
            u64 gi = pack2(g1[j], g1[j]);
            const ulonglong2* row = (const ulonglong2*)&s_w2[j * 64 + q * 16];
            #pragma unroll
            for (int k = 0; k < 4; k++) {
                ulonglong2 m = row[k];
                ffma2(acc[2 * k + 0], gi, m.x);
                ffma2(acc[2 * k + 1], gi, m.y);
            }
        }
        #pragma unroll
        for (int p = 0; p < 8; p++) {
            float a, b; unpack2(acc[p], a, b);
            g2[q * 16 + 2 * p + 0] = silu_f(a * 0.125f);
            g2[q * 16 + 2 * p + 1] = silu_f(b * 0.125f);
        }
    }

    #pragma unroll
    for (int q = 0; q < 4; q++) {
        u64 acc[8];
        #pragma unroll
        for (int p = 0; p < 8; p++) acc[p] = 0ULL;
        #pragma unroll 4
        for (int j = 0; j < 64; j++) {
            u64 gi = pack2(g2[j], g2[j]);
            const ulonglong2* row = (const ulonglong2*)&s_w3[j * 64 + q * 16];
            #pragma unroll
            for (int k = 0; k < 4; k++) {
                ulonglong2 m = row[k];
                ffma2(acc[2 * k + 0], gi, m.x);
                ffma2(acc[2 * k + 1], gi, m.y);
            }
        }
        #pragma unroll
        for (int p = 0; p < 8; p++) {
            float a, b; unpack2(acc[p], a, b);
            float2 o = make_float2(silu_f(a * 0.125f), silu_f(b * 0.125f));
            *(float2*)&d_g3[e * 64 + q * 16 + 2 * p] = o;
        }
    }
}

// ---------------- kernel 5: scatter edges into CSR ----------------
__global__ void k_scatter(const int* __restrict__ edge_dst) {
    int e = blockIdx.x * 256 + threadIdx.x;
    if (e < N_EDGES) {
        int p = atomicAdd(&d_fill[edge_dst[e]], 1);
        d_csr[p] = e;
    }
}

// ---------------- kernel 6: factorized contraction, warp-per-node, per-l ----------------
// Edge phase: lane-local G[k][j] accumulation (pipelined loads).
// Node phase: fused A+C — rebuild m(cu)=Sum_v Ad_v*M[cu,v,:] from smem, consume vs G.
template<int L>
__global__ __launch_bounds__(256, (L == 0) ? 3 : 2) void k_main(
    const int* __restrict__ src, float* __restrict__ out)
{
    constexpr int K   = (L == 0) ? 1 : (L == 1) ? 3 : 5;
    constexpr int OFF = (L == 0) ? 0 : (L == 1) ? 4 : 16;
    extern __shared__ float sM[];   // 16384 floats, v-xor swizzled

    for (int idx = threadIdx.x; idx < 16384; idx += 256) {
        int cu = idx >> 5, vw = idx & 31;
        int v = vw >> 2, w = vw & 3;
        int pv = v ^ ((cu >> 4) & 7);
        sM[(cu << 5) + (pv << 2) + w] = d_Ml[L * 16384 + idx];
    }
    __syncthreads();

    const int wid = threadIdx.x >> 5;
    const int lane = threadIdx.x & 31;
    const u64 ONE2 = pack2(1.0f, 1.0f);

    for (int n = blockIdx.x * 8 + wid; n < N_NODES; n += gridDim.x * 8) {
        int beg = d_rowptr[n], end = d_rowptr[n + 1];
        int deg = end - beg;
        float* od = out + n * OUT_PER_NODE + OFF;
        if (deg == 0) {
            if (lane < 4 * K) od[lane] = 0.0f;
            continue;
        }

        u64 G[K][8];
        #pragma unroll
        for (int k = 0; k < K; k++)
            #pragma unroll
            for (int j = 0; j < 8; j++) G[k][j] = 0ULL;

        // ---- pipelined edge phase ----
        ulonglong2 p01, p23;
        float2 gpn;
        float4 shn = make_float4(0.f, 0.f, 0.f, 0.f);
        float shn2 = 0.f;
        {
            int e0 = d_csr[beg];
            int s0 = src[e0];
            const ulonglong2* ap = (const ulonglong2*)&d_Aip[s0 * 4];
            p01 = ap[0]; p23 = ap[1];
            gpn = *(const float2*)&d_g3[e0 * 64 + 2 * lane];
            if (L == 1) shn = *(const float4*)&d_sh[e0 * 8];
            if (L == 2) { shn2 = d_sh[e0 * 8 + 3]; shn = *(const float4*)&d_sh[e0 * 8 + 4]; }
        }
        for (int i = beg; i < end; i++) {
            u64 aa[4] = {p01.x, p01.y, p23.x, p23.y};
            float2 gp = gpn;
            float4 shc = shn;
            float shc2 = shn2;
            if (i + 1 < end) {
                int e2 = d_csr[i + 1];
                int s2 = src[e2];
                const ulonglong2* ap = (const ulonglong2*)&d_Aip[s2 * 4];
                p01 = ap[0]; p23 = ap[1];
                gpn = *(const float2*)&d_g3[e2 * 64 + 2 * lane];
                if (L == 1) shn = *(const float4*)&d_sh[e2 * 8];
                if (L == 2) { shn2 = d_sh[e2 * 8 + 3]; shn = *(const float4*)&d_sh[e2 * 8 + 4]; }
            }

            u64 g00 = pack2(gp.x, gp.x), g11 = pack2(gp.y, gp.y);
            u64 ff[8];
            #pragma unroll
            for (int j = 0; j < 4; j++) { ff[j] = 0ULL; ffma2(ff[j], g00, aa[j]); }
            #pragma unroll
            for (int j = 0; j < 4; j++) { ff[4 + j] = 0ULL; ffma2(ff[4 + j], g11, aa[j]); }

            if (L == 0) {
                #pragma unroll
                for (int j = 0; j < 8; j++) ffma2(G[0][j], ff[j], ONE2);
            } else if (L == 1) {
                float shv[3] = {shc.x, shc.y, shc.z};
                #pragma unroll
                for (int k = 0; k < 3; k++) {
                    u64 ss = pack2(shv[k], shv[k]);
                    #pragma unroll
                    for (int j = 0; j < 8; j++) ffma2(G[k][j], ff[j], ss);
                }
            } else {
                float shv[5] = {shc2, shc.x, shc.y, shc.z, shc.w};
                #pragma unroll
                for (int k = 0; k < 5; k++) {
                    u64 ss = pack2(shv[k], shv[k]);
                    #pragma unroll
                    for (int j = 0; j < 8; j++) ffma2(G[k][j], ff[j], ss);
                }
            }
        }

        // ---- fused A+C phase: rebuild m(cu) from smem, consume against G ----
        float Ad[8];
        {
            const float4* Ai4 = (const float4*)&d_Ai[n * 8];
            float4 b0 = Ai4[0], b1 = Ai4[1];
            Ad[0] = b0.x; Ad[1] = b0.y; Ad[2] = b0.z; Ad[3] = b0.w;
            Ad[4] = b1.x; Ad[5] = b1.y; Ad[6] = b1.z; Ad[7] = b1.w;
        }
        u64 acc[K][2];
        #pragma unroll
        for (int k = 0; k < K; k++) { acc[k][0] = 0ULL; acc[k][1] = 0ULL; }

        #pragma unroll
        for (int j = 0; j < 8; j++) {
            u64 m00, m01, m10, m11;
            {
                int base0 = (lane * 16 + 2 * j) * 32;
                u64 a0 = 0ULL, a1 = 0ULL, b0 = 0ULL, b1 = 0ULL;
                #pragma unroll
                for (int v = 0; v < 8; v++) {
                    u64 ad = pack2(Ad[v], Ad[v]);
                    ulonglong2 mmA =
                        *(const ulonglong2*)&sM[base0 + ((v ^ (lane & 7)) << 2)];
                    ulonglong2 mmB =
                        *(const ulonglong2*)&sM[base0 + 32 + ((v ^ (lane & 7)) << 2)];
                    ffma2(a0, ad, mmA.x);
                    ffma2(a1, ad, mmA.y);
                    ffma2(b0, ad, mmB.x);
                    ffma2(b1, ad, mmB.y);
                }
                m00 = a0; m01 = a1; m10 = b0; m11 = b1;
            }
            #pragma unroll
            for (int k = 0; k < K; k++) {
                float ga, gb; unpack2(G[k][j], ga, gb);
                u64 gaa = pack2(ga, ga), gbb = pack2(gb, gb);
                ffma2(acc[k][0], gaa, m00);
                ffma2(acc[k][1], gaa, m01);
                ffma2(acc[k][0], gbb, m10);
                ffma2(acc[k][1], gbb, m11);
            }
        }

        // ---- butterfly reduce (once per node) ----
        #pragma unroll
        for (int off = 16; off; off >>= 1) {
            #pragma unroll
            for (int k = 0; k < K; k++) {
                u64 t0 = __shfl_xor_sync(0xffffffffu, acc[k][0], off);
                u64 t1 = __shfl_xor_sync(0xffffffffu, acc[k][1], off);
                ffma2(acc[k][0], t0, ONE2);
                ffma2(acc[k][1], t1, ONE2);
            }
        }

        if (lane == 0) {
            float sc = (1.0f / 64.0f) / (float)deg;
            #pragma unroll
            for (int k = 0; k < K; k++) {
                float W[4];
                unpack2(acc[k][0], W[0], W[1]);
                unpack2(acc[k][1], W[2], W[3]);
                #pragma unroll
                for (int w = 0; w < 4; w++) {
                    if (L == 0)      od[w] = W[w] * sc;
                    else if (L == 1) od[w * 3 + k] = W[w] * sc;
                    else             od[w * 5 + k] = W[w] * sc;
                }
            }
        }
    }
}

// ---------------- launch ----------------
extern "C" void kernel_launch(void* const* d_in, const int* in_sizes, int n_in,
                              void* d_out, int out_size) {
    const float* pos      = (const float*)d_in[0];
    const int*   A        = (const int*)d_in[1];
    const int*   batch    = (const int*)d_in[2];
    const int*   edge_src = (const int*)d_in[3];
    const int*   edge_dst = (const int*)d_in[4];
    const float* shifts   = (const float*)d_in[5];
    const float* cell     = (const float*)d_in[6];
    const float* emb      = (const float*)d_in[7];
    const float* fit_w1   = (const float*)d_in[8];
    const float* fit_b1   = (const float*)d_in[9];
    const float* fit_w2   = (const float*)d_in[10];
    const float* fit_b2   = (const float*)d_in[11];
    const float* fit_w3   = (const float*)d_in[12];
    const float* fit_b3   = (const float*)d_in[13];
    const float* fc_w1    = (const float*)d_in[14];
    const float* fc_w2    = (const float*)d_in[15];
    const float* fc_w3    = (const float*)d_in[16];
    const float* fc_w4    = (const float*)d_in[17];
    float* out = (float*)d_out;

    cudaFuncSetAttribute(k_main<0>, cudaFuncAttributeMaxDynamicSharedMemorySize, 65536);
    cudaFuncSetAttribute(k_main<1>, cudaFuncAttributeMaxDynamicSharedMemorySize, 65536);
    cudaFuncSetAttribute(k_main<2>, cudaFuncAttributeMaxDynamicSharedMemorySize, 65536);

    k_zero<<<(N_NODES + 255) / 256, 256>>>();
    k_prepcount<<<NODE_BLOCKS + PERM_BLOCKS + (N_EDGES / 256), 256>>>(
        emb, fit_w1, fit_b1, fit_w2, fit_b2, fit_w3, fit_b3, A, fc_w4, edge_dst);
    k_scan<<<1, 1024>>>();
    k_radial<<<N_EDGES / 128, 128>>>(pos, batch, edge_src, edge_dst,
                                     shifts, cell, fc_w1, fc_w2, fc_w3);
    k_scatter<<<N_EDGES / 256, 256>>>(edge_dst);
    k_main<0><<<444, 256, 65536>>>(edge_src, out);
    k_main<1><<<296, 256, 65536>>>(edge_src, out);
    k_main<2><<<296, 256, 65536>>>(edge_src, out);
}

// round 11
// speedup vs baseline: 1.3382x; 1.0279x over previous
#include <cuda_runtime.h>
#include <math.h>

#define N_NODES 20000
#define N_EDGES 160000
#define OUT_PER_NODE 36

typedef unsigned long long u64;

// ---------------- packed f32x2 helpers ----------------
__device__ __forceinline__ u64 pack2(float a, float b) {
    u64 r; asm("mov.b64 %0, {%1,%2};" : "=l"(r) : "f"(a), "f"(b)); return r;
}
__device__ __forceinline__ void unpack2(u64 v, float& a, float& b) {
    asm("mov.b64 {%0,%1}, %2;" : "=f"(a), "=f"(b) : "l"(v));
}
__device__ __forceinline__ void ffma2(u64& d, u64 a, u64 b) {
    asm("fma.rn.f32x2 %0, %1, %2, %0;" : "+l"(d) : "l"(a), "l"(b));
}
__device__ __forceinline__ float silu_f(float x) {
    return __fdividef(x, 1.0f + __expf(-x));
}

// ---------------- scratch ----------------
__device__ float d_Ai[N_NODES * 8];
__device__ u64   d_Aip[N_NODES * 4];        // (Ai[2j],Ai[2j+1]) pairs
__device__ float d_g3[N_EDGES * 64];        // [e][c]  (edge-indexed)
__device__ float d_sh[N_EDGES * 8];         // [e][sh1_0..2, sh2_0..4]
__device__ float d_Ml[3 * 512 * 32];        // [l][cu][v*4+w]
__device__ int   d_deg[N_NODES];
__device__ int   d_rowptr[N_NODES + 1];
__device__ int   d_fill[N_NODES];
__device__ int   d_csr[N_EDGES];

// ---------------- kernel 1: zero degree counters ----------------
__global__ void k_zero() {
    int i = blockIdx.x * blockDim.x + threadIdx.x;
    if (i < N_NODES) d_deg[i] = 0;
}

// ---------------- kernel 2: node MLP + M permute + degree count ----------------
#define NODE_BLOCKS 79
#define PERM_BLOCKS 192
__global__ __launch_bounds__(256) void k_prepcount(
    const float* __restrict__ emb_table,
    const float* __restrict__ w1, const float* __restrict__ b1,
    const float* __restrict__ w2, const float* __restrict__ b2,
    const float* __restrict__ w3, const float* __restrict__ b3,
    const int* __restrict__ A,
    const float* __restrict__ fc_w4,
    const int* __restrict__ edge_dst)
{
    int tid = threadIdx.x;
    int bx = blockIdx.x;
    if (bx >= NODE_BLOCKS + PERM_BLOCKS) {
        int e = (bx - NODE_BLOCKS - PERM_BLOCKS) * 256 + tid;
        if (e < N_EDGES) atomicAdd(&d_deg[edge_dst[e]], 1);
        return;
    }
    if (bx >= NODE_BLOCKS) {
        // fc_w4 [c][l][u][v][w] -> d_Ml[l][(c*8+u)][v*4+w]
        int idx = (bx - NODE_BLOCKS) * 256 + tid;   // < 49152
        int c = idx / 768;
        int rem = idx - c * 768;
        int l = rem / 256;
        int rem2 = rem - l * 256;
        int u = rem2 / 32;
        int vw = rem2 - u * 32;
        d_Ml[l * (512 * 32) + (c * 8 + u) * 32 + vw] = fc_w4[idx];
        return;
    }

    __shared__ __align__(16) float s_w1[16 * 64];
    __shared__ __align__(16) float s_w2[64 * 32];
    __shared__ __align__(16) float s_w3[32 * 8];
    __shared__ float s_b1[64];
    __shared__ float s_b2[32];
    __shared__ float s_b3[8];
    for (int i = tid; i < 16 * 64; i += 256) s_w1[i] = w1[i];
    for (int i = tid; i < 64 * 32; i += 256) s_w2[i] = w2[i];
    for (int i = tid; i < 32 * 8;  i += 256) s_w3[i] = w3[i];
    if (tid < 64) s_b1[tid] = b1[tid];
    if (tid < 32) s_b2[tid] = b2[tid];
    if (tid < 8)  s_b3[tid] = b3[tid];
    __syncthreads();

    int n = bx * 256 + tid;
    if (n >= N_NODES) return;

    int a = A[n];
    float e[16];
    #pragma unroll
    for (int i = 0; i < 16; i++) e[i] = emb_table[a * 16 + i];

    float h1[64];
    #pragma unroll
    for (int j = 0; j < 64; j++) h1[j] = s_b1[j];
    #pragma unroll
    for (int i = 0; i < 16; i++) {
        float ei = e[i];
        #pragma unroll
        for (int j = 0; j < 64; j++) h1[j] += ei * s_w1[i * 64 + j];
    }
    #pragma unroll
    for (int j = 0; j < 64; j++) h1[j] = silu_f(h1[j]);

    float h2[32];
    #pragma unroll
    for (int j = 0; j < 32; j++) h2[j] = s_b2[j];
    #pragma unroll
    for (int i = 0; i < 64; i++) {
        float hi = h1[i];
        #pragma unroll
        for (int j = 0; j < 32; j++) h2[j] += hi * s_w2[i * 32 + j];
    }
    #pragma unroll
    for (int j = 0; j < 32; j++) h2[j] = silu_f(h2[j]);

    float ai[8];
    #pragma unroll
    for (int j = 0; j < 8; j++) ai[j] = s_b3[j];
    #pragma unroll
    for (int i = 0; i < 32; i++) {
        float hi = h2[i];
        #pragma unroll
        for (int j = 0; j < 8; j++) ai[j] += hi * s_w3[i * 8 + j];
    }
    #pragma unroll
    for (int j = 0; j < 8; j++) d_Ai[n * 8 + j] = ai[j];
    #pragma unroll
    for (int j = 0; j < 4; j++) d_Aip[n * 4 + j] = pack2(ai[2 * j], ai[2 * j + 1]);
}

// ---------------- kernel 3: single-block prefix scan ----------------
__global__ __launch_bounds__(1024) void k_scan() {
    __shared__ int sbuf[1024];
    int tid = threadIdx.x;
    int carry = 0;
    if (tid == 0) d_rowptr[0] = 0;
    for (int base = 0; base < N_NODES; base += 1024) {
        int i = base + tid;
        int v = (i < N_NODES) ? d_deg[i] : 0;
        sbuf[tid] = v;
        __syncthreads();
        for (int off = 1; off < 1024; off <<= 1) {
            int t = (tid >= off) ? sbuf[tid - off] : 0;
            __syncthreads();
            sbuf[tid] += t;
            __syncthreads();
        }
        if (i < N_NODES) d_rowptr[i + 1] = carry + sbuf[tid];
        int tot = sbuf[1023];
        __syncthreads();
        carry += tot;
    }
    __syncthreads();
    for (int i = tid; i < N_NODES; i += 1024) d_fill[i] = d_rowptr[i];
}

// ---------------- geometry helper ----------------
__device__ __forceinline__ void edge_geom(
    const float* __restrict__ pos, const int* __restrict__ batch,
    const float* __restrict__ shifts, const float* __restrict__ cell,
    int e, int s, int d, float& ex, float& ey, float& ez, float& r)
{
    float sx = shifts[e * 3 + 0], sy = shifts[e * 3 + 1], sz = shifts[e * 3 + 2];
    int b = batch[s];
    const float* C = cell + b * 9;
    float shx = sx * C[0] + sy * C[3] + sz * C[6];
    float shy = sx * C[1] + sy * C[4] + sz * C[7];
    float shz = sx * C[2] + sy * C[5] + sz * C[8];
    ex = pos[d * 3 + 0] - pos[s * 3 + 0] + shx;
    ey = pos[d * 3 + 1] - pos[s * 3 + 1] + shy;
    ez = pos[d * 3 + 2] - pos[s * 3 + 2] + shz;
    r = sqrtf(ex * ex + ey * ey + ez * ez);
}

// ---------------- kernel 4 (launch slot 4): radial chain + sh, edge-indexed ----------------
__global__ __launch_bounds__(128, 3) void k_radial(
    const float* __restrict__ pos, const int* __restrict__ batch,
    const int* __restrict__ src, const int* __restrict__ dst,
    const float* __restrict__ shifts, const float* __restrict__ cell,
    const float* __restrict__ fw1, const float* __restrict__ fw2,
    const float* __restrict__ fw3)
{
    __shared__ __align__(16) float s_w1[16 * 64];
    __shared__ __align__(16) float s_w2[64 * 64];
    __shared__ __align__(16) float s_w3[64 * 64];
    int tid = threadIdx.x;
    for (int i = tid; i < 16 * 64; i += 128) s_w1[i] = fw1[i];
    for (int i = tid; i < 64 * 64; i += 128) s_w2[i] = fw2[i];
    for (int i = tid; i < 64 * 64; i += 128) s_w3[i] = fw3[i];
    __syncthreads();

    int e = blockIdx.x * 128 + tid;        // edge-indexed (no CSR dependency)

    int s = src[e], d = dst[e];
    float ex, ey, ez, r;
    edge_geom(pos, batch, shifts, cell, e, s, d, ex, ey, ez, r);

    // spherical harmonics
    {
        float inv_r = __fdividef(1.0f, fmaxf(r, 1e-9f));
        float x = ex * inv_r, y = ey * inv_r, z = ez * inv_r;
        const float s3 = 1.7320508075688772f;
        const float s15 = 3.872983346207417f;
        const float s5 = 2.23606797749979f;
        float4 o0 = make_float4(s3 * y, s3 * z, s3 * x, s15 * x * y);
        float4 o1 = make_float4(s15 * y * z, 0.5f * s5 * (3.0f * z * z - 1.0f),
                                s15 * x * z, 0.5f * s15 * (x * x - y * y));
        *(float4*)&d_sh[e * 8 + 0] = o0;
        *(float4*)&d_sh[e * 8 + 4] = o1;
    }

    const float step = 5.0f / 17.0f;
    const float inv_step = 17.0f / 5.0f;
    const float rb_scale = 4.0f / 1.12f;

    float rb[16];
    #pragma unroll
    for (int j = 0; j < 16; j++) {
        float c = step * (float)(j + 1);
        float t = (r - c) * inv_step;
        rb[j] = __expf(-t * t) * rb_scale;
    }

    float g1[64];
    #pragma unroll
    for (int h = 0; h < 2; h++) {
        u64 acc[16];
        #pragma unroll
        for (int p = 0; p < 16; p++) acc[p] = 0ULL;
        #pragma unroll 4
        for (int j = 0; j < 16; j++) {
            u64 rr = pack2(rb[j], rb[j]);
            const ulonglong2* row = (const ulonglong2*)&s_w1[j * 64 + h * 32];
            #pragma unroll
            for (int k = 0; k < 8; k++) {
                ulonglong2 m = row[k];
                ffma2(acc[2 * k + 0], rr, m.x);
                ffma2(acc[2 * k + 1], rr, m.y);
            }
        }
        #pragma unroll
        for (int p = 0; p < 16; p++) {
            float a, b; unpack2(acc[p], a, b);
            g1[h * 32 + 2 * p + 0] = silu_f(a * 0.25f);
            g1[h * 32 + 2 * p + 1] = silu_f(b * 0.25f);
        }
    }

    float g2[64];
    #pragma unroll
    for (int q = 0; q < 4; q++) {
        u64 acc[8];
        #pragma unroll
        for (int p = 0; p < 8; p++) acc[p] = 0ULL;
        #pragma unroll 4
        for (int j = 0; j < 64; j++) {
            u64 gi = pack2(g1[j], g1[j]);
            const ulonglong2* row = (const ulonglong2*)&s_w2[j * 64 + q * 16];
            #pragma unroll
            for (int k = 0; k < 4; k++) {
                ulonglong2 m = row[k];
                ffma2(acc[2 * k + 0], gi, m.x);
                ffma2(acc[2 * k + 1], gi, m.y);
            }
        }
        #pragma unroll
        for (int p = 0; p < 8; p++) {
            float a, b; unpack2(acc[p], a, b);
            g2[q * 16 + 2 * p + 0] = silu_f(a * 0.125f);
            g2[q * 16 + 2 * p + 1] = silu_f(b * 0.125f);
        }
    }

    #pragma unroll
    for (int q = 0; q < 4; q++) {
        u64 acc[8];
        #pragma unroll
        for (int p = 0; p < 8; p++) acc[p] = 0ULL;
        #pragma unroll 4
        for (int j = 0; j < 64; j++) {
            u64 gi = pack2(g2[j], g2[j]);
            const ulonglong2* row = (const ulonglong2*)&s_w3[j * 64 + q * 16];
            #pragma unroll
            for (int k = 0; k < 4; k++) {
                ulonglong2 m = row[k];
                ffma2(acc[2 * k + 0], gi, m.x);
                ffma2(acc[2 * k + 1], gi, m.y);
            }
        }
        #pragma unroll
        for (int p = 0; p < 8; p++) {
            float a, b; unpack2(acc[p], a, b);
            float2 o = make_float2(silu_f(a * 0.125f), silu_f(b * 0.125f));
            *(float2*)&d_g3[e * 64 + q * 16 + 2 * p] = o;
        }
    }
}

// ---------------- kernel 5: scatter edges into CSR ----------------
__global__ void k_scatter(const int* __restrict__ edge_dst) {
    int e = blockIdx.x * 256 + threadIdx.x;
    if (e < N_EDGES) {
        int p = atomicAdd(&d_fill[edge_dst[e]], 1);
        d_csr[p] = e;
    }
}

// ---------------- kernel 6: factorized contraction, warp-per-node, per-l ----------------
// Edge phase: lane-local G[k][j] accumulation (pipelined loads).
// Node phase: fused A+C — rebuild m(cu)=Sum_v Ad_v*M[cu,v,:] from smem, consume vs G.
template<int L>
__global__ __launch_bounds__(256, (L == 0) ? 3 : 2) void k_main(
    const int* __restrict__ src, float* __restrict__ out)
{
    constexpr int K   = (L == 0) ? 1 : (L == 1) ? 3 : 5;
    constexpr int OFF = (L == 0) ? 0 : (L == 1) ? 4 : 16;
    extern __shared__ float sM[];   // 16384 floats, v-xor swizzled

    for (int idx = threadIdx.x; idx < 16384; idx += 256) {
        int cu = idx >> 5, vw = idx & 31;
        int v = vw >> 2, w = vw & 3;
        int pv = v ^ ((cu >> 4) & 7);
        sM[(cu << 5) + (pv << 2) + w] = d_Ml[L * 16384 + idx];
    }
    __syncthreads();

    const int wid = threadIdx.x >> 5;
    const int lane = threadIdx.x & 31;
    const u64 ONE2 = pack2(1.0f, 1.0f);

    for (int n = blockIdx.x * 8 + wid; n < N_NODES; n += gridDim.x * 8) {
        int beg = d_rowptr[n], end = d_rowptr[n + 1];
        int deg = end - beg;
        float* od = out + n * OUT_PER_NODE + OFF;
        if (deg == 0) {
            if (lane < 4 * K) od[lane] = 0.0f;
            continue;
        }

        u64 G[K][8];
        #pragma unroll
        for (int k = 0; k < K; k++)
            #pragma unroll
            for (int j = 0; j < 8; j++) G[k][j] = 0ULL;

        // ---- pipelined edge phase ----
        ulonglong2 p01, p23;
        float2 gpn;
        float4 shn = make_float4(0.f, 0.f, 0.f, 0.f);
        float shn2 = 0.f;
        {
            int e0 = d_csr[beg];
            int s0 = src[e0];
            const ulonglong2* ap = (const ulonglong2*)&d_Aip[s0 * 4];
            p01 = ap[0]; p23 = ap[1];
            gpn = *(const float2*)&d_g3[e0 * 64 + 2 * lane];
            if (L == 1) shn = *(const float4*)&d_sh[e0 * 8];
            if (L == 2) { shn2 = d_sh[e0 * 8 + 3]; shn = *(const float4*)&d_sh[e0 * 8 + 4]; }
        }
        for (int i = beg; i < end; i++) {
            u64 aa[4] = {p01.x, p01.y, p23.x, p23.y};
            float2 gp = gpn;
            float4 shc = shn;
            float shc2 = shn2;
            if (i + 1 < end) {
                int e2 = d_csr[i + 1];
                int s2 = src[e2];
                const ulonglong2* ap = (const ulonglong2*)&d_Aip[s2 * 4];
                p01 = ap[0]; p23 = ap[1];
                gpn = *(const float2*)&d_g3[e2 * 64 + 2 * lane];
                if (L == 1) shn = *(const float4*)&d_sh[e2 * 8];
                if (L == 2) { shn2 = d_sh[e2 * 8 + 3]; shn = *(const float4*)&d_sh[e2 * 8 + 4]; }
            }

            u64 g00 = pack2(gp.x, gp.x), g11 = pack2(gp.y, gp.y);
            u64 ff[8];
            #pragma unroll
            for (int j = 0; j < 4; j++) { ff[j] = 0ULL; ffma2(ff[j], g00, aa[j]); }
            #pragma unroll
            for (int j = 0; j < 4; j++) { ff[4 + j] = 0ULL; ffma2(ff[4 + j], g11, aa[j]); }

            if (L == 0) {
                #pragma unroll
                for (int j = 0; j < 8; j++) ffma2(G[0][j], ff[j], ONE2);
            } else if (L == 1) {
                float shv[3] = {shc.x, shc.y, shc.z};
                #pragma unroll
                for (int k = 0; k < 3; k++) {
                    u64 ss = pack2(shv[k], shv[k]);
                    #pragma unroll
                    for (int j = 0; j < 8; j++) ffma2(G[k][j], ff[j], ss);
                }
            } else {
                float shv[5] = {shc2, shc.x, shc.y, shc.z, shc.w};
                #pragma unroll
                for (int k = 0; k < 5; k++) {
                    u64 ss = pack2(shv[k], shv[k]);
                    #pragma unroll
                    for (int j = 0; j < 8; j++) ffma2(G[k][j], ff[j], ss);
                }
            }
        }

        // ---- fused A+C phase: rebuild m(cu) from smem, consume against G ----
        float Ad[8];
        {
            const float4* Ai4 = (const float4*)&d_Ai[n * 8];
            float4 b0 = Ai4[0], b1 = Ai4[1];
            Ad[0] = b0.x; Ad[1] = b0.y; Ad[2] = b0.z; Ad[3] = b0.w;
            Ad[4] = b1.x; Ad[5] = b1.y; Ad[6] = b1.z; Ad[7] = b1.w;
        }
        u64 acc[K][2];
        #pragma unroll
        for (int k = 0; k < K; k++) { acc[k][0] = 0ULL; acc[k][1] = 0ULL; }

        #pragma unroll
        for (int j = 0; j < 8; j++) {
            u64 m00, m01, m10, m11;
            {
                int base0 = (lane * 16 + 2 * j) * 32;
                u64 a0 = 0ULL, a1 = 0ULL, b0 = 0ULL, b1 = 0ULL;
                #pragma unroll
                for (int v = 0; v < 8; v++) {
                    u64 ad = pack2(Ad[v], Ad[v]);
                    ulonglong2 mmA =
                        *(const ulonglong2*)&sM[base0 + ((v ^ (lane & 7)) << 2)];
                    ulonglong2 mmB =
                        *(const ulonglong2*)&sM[base0 + 32 + ((v ^ (lane & 7)) << 2)];
                    ffma2(a0, ad, mmA.x);
                    ffma2(a1, ad, mmA.y);
                    ffma2(b0, ad, mmB.x);
                    ffma2(b1, ad, mmB.y);
                }
                m00 = a0; m01 = a1; m10 = b0; m11 = b1;
            }
            #pragma unroll
            for (int k = 0; k < K; k++) {
                float ga, gb; unpack2(G[k][j], ga, gb);
                u64 gaa = pack2(ga, ga), gbb = pack2(gb, gb);
                ffma2(acc[k][0], gaa, m00);
                ffma2(acc[k][1], gaa, m01);
                ffma2(acc[k][0], gbb, m10);
                ffma2(acc[k][1], gbb, m11);
            }
        }

        // ---- butterfly reduce (once per node) ----
        #pragma unroll
        for (int off = 16; off; off >>= 1) {
            #pragma unroll
            for (int k = 0; k < K; k++) {
                u64 t0 = __shfl_xor_sync(0xffffffffu, acc[k][0], off);
                u64 t1 = __shfl_xor_sync(0xffffffffu, acc[k][1], off);
                ffma2(acc[k][0], t0, ONE2);
                ffma2(acc[k][1], t1, ONE2);
            }
        }

        if (lane == 0) {
            float sc = (1.0f / 64.0f) / (float)deg;
            #pragma unroll
            for (int k = 0; k < K; k++) {
                float W[4];
                unpack2(acc[k][0], W[0], W[1]);
                unpack2(acc[k][1], W[2], W[3]);
                #pragma unroll
                for (int w = 0; w < 4; w++) {
                    if (L == 0)      od[w] = W[w] * sc;
                    else if (L == 1) od[w * 3 + k] = W[w] * sc;
                    else             od[w * 5 + k] = W[w] * sc;
                }
            }
        }
    }
}

// ---------------- launch ----------------
extern "C" void kernel_launch(void* const* d_in, const int* in_sizes, int n_in,
                              void* d_out, int out_size) {
    const float* pos      = (const float*)d_in[0];
    const int*   A        = (const int*)d_in[1];
    const int*   batch    = (const int*)d_in[2];
    const int*   edge_src = (const int*)d_in[3];
    const int*   edge_dst = (const int*)d_in[4];
    const float* shifts   = (const float*)d_in[5];
    const float* cell     = (const float*)d_in[6];
    const float* emb      = (const float*)d_in[7];
    const float* fit_w1   = (const float*)d_in[8];
    const float* fit_b1   = (const float*)d_in[9];
    const float* fit_w2   = (const float*)d_in[10];
    const float* fit_b2   = (const float*)d_in[11];
    const float* fit_w3   = (const float*)d_in[12];
    const float* fit_b3   = (const float*)d_in[13];
    const float* fc_w1    = (const float*)d_in[14];
    const float* fc_w2    = (const float*)d_in[15];
    const float* fc_w3    = (const float*)d_in[16];
    const float* fc_w4    = (const float*)d_in[17];
    float* out = (float*)d_out;

    cudaFuncSetAttribute(k_main<0>, cudaFuncAttributeMaxDynamicSharedMemorySize, 65536);
    cudaFuncSetAttribute(k_main<1>, cudaFuncAttributeMaxDynamicSharedMemorySize, 65536);
    cudaFuncSetAttribute(k_main<2>, cudaFuncAttributeMaxDynamicSharedMemorySize, 65536);

    k_zero<<<(N_NODES + 255) / 256, 256>>>();
    k_prepcount<<<NODE_BLOCKS + PERM_BLOCKS + (N_EDGES / 256), 256>>>(
        emb, fit_w1, fit_b1, fit_w2, fit_b2, fit_w3, fit_b3, A, fc_w4, edge_dst);
    k_scan<<<1, 1024>>>();
    k_radial<<<N_EDGES / 128, 128>>>(pos, batch, edge_src, edge_dst,
                                     shifts, cell, fc_w1, fc_w2, fc_w3);
    k_scatter<<<N_EDGES / 256, 256>>>(edge_dst);
    k_main<0><<<444, 256, 65536>>>(edge_src, out);
    k_main<1><<<296, 256, 65536>>>(edge_src, out);
    k_main<2><<<296, 256, 65536>>>(edge_src, out);
}

// round 12
// speedup vs baseline: 1.5663x; 1.1704x over previous
#include <cuda_runtime.h>
#include <math.h>

#define N_NODES 20000
#define N_EDGES 160000
#define OUT_PER_NODE 36

typedef unsigned long long u64;

__device__ __forceinline__ u64 pack2(float a, float b) {
    u64 r; asm("mov.b64 %0, {%1,%2};" : "=l"(r) : "f"(a), "f"(b)); return r;
}
__device__ __forceinline__ void unpack2(u64 v, float& a, float& b) {
    asm("mov.b64 {%0,%1}, %2;" : "=f"(a), "=f"(b) : "l"(v));
}
__device__ __forceinline__ void ffma2(u64& d, u64 a, u64 b) {
    asm("fma.rn.f32x2 %0, %1, %2, %0;" : "+l"(d) : "l"(a), "l"(b));
}
__device__ __forceinline__ float silu_f(float x) {
    return __fdividef(x, 1.0f + __expf(-x));
}

// ---------------- scratch ----------------
__device__ float d_Ai[N_NODES * 8];
__device__ u64   d_Aip[N_NODES * 4];
__device__ float d_g3[N_EDGES * 64];        // [e][c]
__device__ float d_sh[N_EDGES * 8];
__device__ float d_Ml[3 * 512 * 32];        // [l][cu][v*4+w]
__device__ int   d_deg[N_NODES];
__device__ int   d_rowptr[N_NODES + 1];
__device__ int   d_fill[N_NODES];
__device__ int   d_csr[N_EDGES];

__global__ void k_zero() {
    int i = blockIdx.x * blockDim.x + threadIdx.x;
    if (i < N_NODES) d_deg[i] = 0;
}

// ---------------- kernel 2: node MLP + M permute + degree count ----------------
#define NODE_BLOCKS 79
#define PERM_BLOCKS 192
__global__ __launch_bounds__(256) void k_prepcount(
    const float* __restrict__ emb_table,
    const float* __restrict__ w1, const float* __restrict__ b1,
    const float* __restrict__ w2, const float* __restrict__ b2,
    const float* __restrict__ w3, const float* __restrict__ b3,
    const int* __restrict__ A,
    const float* __restrict__ fc_w4,
    const int* __restrict__ edge_dst)
{
    int tid = threadIdx.x;
    int bx = blockIdx.x;
    if (bx >= NODE_BLOCKS + PERM_BLOCKS) {
        int e = (bx - NODE_BLOCKS - PERM_BLOCKS) * 256 + tid;
        if (e < N_EDGES) atomicAdd(&d_deg[edge_dst[e]], 1);
        return;
    }
    if (bx >= NODE_BLOCKS) {
        int idx = (bx - NODE_BLOCKS) * 256 + tid;
        int c = idx / 768;
        int rem = idx - c * 768;
        int l = rem / 256;
        int rem2 = rem - l * 256;
        int u = rem2 / 32;
        int vw = rem2 - u * 32;
        d_Ml[l * (512 * 32) + (c * 8 + u) * 32 + vw] = fc_w4[idx];
        return;
    }

    __shared__ __align__(16) float s_w1[16 * 64];
    __shared__ __align__(16) float s_w2[64 * 32];
    __shared__ __align__(16) float s_w3[32 * 8];
    __shared__ float s_b1[64];
    __shared__ float s_b2[32];
    __shared__ float s_b3[8];
    for (int i = tid; i < 16 * 64; i += 256) s_w1[i] = w1[i];
    for (int i = tid; i < 64 * 32; i += 256) s_w2[i] = w2[i];
    for (int i = tid; i < 32 * 8;  i += 256) s_w3[i] = w3[i];
    if (tid < 64) s_b1[tid] = b1[tid];
    if (tid < 32) s_b2[tid] = b2[tid];
    if (tid < 8)  s_b3[tid] = b3[tid];
    __syncthreads();

    int n = bx * 256 + tid;
    if (n >= N_NODES) return;

    int a = A[n];
    float e[16];
    #pragma unroll
    for (int i = 0; i < 16; i++) e[i] = emb_table[a * 16 + i];

    float h1[64];
    #pragma unroll
    for (int j = 0; j < 64; j++) h1[j] = s_b1[j];
    #pragma unroll
    for (int i = 0; i < 16; i++) {
        float ei = e[i];
        #pragma unroll
        for (int j = 0; j < 64; j++) h1[j] += ei * s_w1[i * 64 + j];
    }
    #pragma unroll
    for (int j = 0; j < 64; j++) h1[j] = silu_f(h1[j]);

    float h2[32];
    #pragma unroll
    for (int j = 0; j < 32; j++) h2[j] = s_b2[j];
    #pragma unroll
    for (int i = 0; i < 64; i++) {
        float hi = h1[i];
        #pragma unroll
        for (int j = 0; j < 32; j++) h2[j] += hi * s_w2[i * 32 + j];
    }
    #pragma unroll
    for (int j = 0; j < 32; j++) h2[j] = silu_f(h2[j]);

    float ai[8];
    #pragma unroll
    for (int j = 0; j < 8; j++) ai[j] = s_b3[j];
    #pragma unroll
    for (int i = 0; i < 32; i++) {
        float hi = h2[i];
        #pragma unroll
        for (int j = 0; j < 8; j++) ai[j] += hi * s_w3[i * 8 + j];
    }
    #pragma unroll
    for (int j = 0; j < 8; j++) d_Ai[n * 8 + j] = ai[j];
    #pragma unroll
    for (int j = 0; j < 4; j++) d_Aip[n * 4 + j] = pack2(ai[2 * j], ai[2 * j + 1]);
}

// ---------------- kernel 3: single-block prefix scan ----------------
__global__ __launch_bounds__(1024) void k_scan() {
    __shared__ int sbuf[1024];
    int tid = threadIdx.x;
    int carry = 0;
    if (tid == 0) d_rowptr[0] = 0;
    for (int base = 0; base < N_NODES; base += 1024) {
        int i = base + tid;
        int v = (i < N_NODES) ? d_deg[i] : 0;
        sbuf[tid] = v;
        __syncthreads();
        for (int off = 1; off < 1024; off <<= 1) {
            int t = (tid >= off) ? sbuf[tid - off] : 0;
            __syncthreads();
            sbuf[tid] += t;
            __syncthreads();
        }
        if (i < N_NODES) d_rowptr[i + 1] = carry + sbuf[tid];
        int tot = sbuf[1023];
        __syncthreads();
        carry += tot;
    }
    __syncthreads();
    for (int i = tid; i < N_NODES; i += 1024) d_fill[i] = d_rowptr[i];
}

// ---------------- geometry helper ----------------
__device__ __forceinline__ void edge_geom(
    const float* __restrict__ pos, const int* __restrict__ batch,
    const float* __restrict__ shifts, const float* __restrict__ cell,
    int e, int s, int d, float& ex, float& ey, float& ez, float& r)
{
    float sx = shifts[e * 3 + 0], sy = shifts[e * 3 + 1], sz = shifts[e * 3 + 2];
    int b = batch[s];
    const float* C = cell + b * 9;
    float shx = sx * C[0] + sy * C[3] + sz * C[6];
    float shy = sx * C[1] + sy * C[4] + sz * C[7];
    float shz = sx * C[2] + sy * C[5] + sz * C[8];
    ex = pos[d * 3 + 0] - pos[s * 3 + 0] + shx;
    ey = pos[d * 3 + 1] - pos[s * 3 + 1] + shy;
    ez = pos[d * 3 + 2] - pos[s * 3 + 2] + shz;
    r = sqrtf(ex * ex + ey * ey + ez * ez);
}

// ---------------- tiled MLP layer helper ----------------
// inb: [DEPTH][128] smem, outb: [64][128] smem, w: [DEPTH][64]
// thread tile: 8 edges (quads at eg*4 and eg*4+64) x 8 outputs (og*8..+7)
template<int DEPTH>
__device__ __forceinline__ void gemm_layer(
    const float* __restrict__ inb, float* __restrict__ outb,
    const float* __restrict__ w, float scale, int eg, int og)
{
    const int e_lo = eg * 4;
    const int e_hi = eg * 4 + 64;
    u64 acc[8][4];
    #pragma unroll
    for (int o = 0; o < 8; o++)
        #pragma unroll
        for (int k = 0; k < 4; k++) acc[o][k] = 0ULL;

    #pragma unroll 4
    for (int i = 0; i < DEPTH; i++) {
        ulonglong2 a0 = *(const ulonglong2*)&inb[i * 128 + e_lo];
        ulonglong2 a1 = *(const ulonglong2*)&inb[i * 128 + e_hi];
        float4 w0 = *(const float4*)&w[i * 64 + og * 8];
        float4 w1 = *(const float4*)&w[i * 64 + og * 8 + 4];
        float wv[8] = {w0.x, w0.y, w0.z, w0.w, w1.x, w1.y, w1.z, w1.w};
        #pragma unroll
        for (int o = 0; o < 8; o++) {
            u64 wd = pack2(wv[o], wv[o]);
            ffma2(acc[o][0], wd, a0.x);
            ffma2(acc[o][1], wd, a0.y);
            ffma2(acc[o][2], wd, a1.x);
            ffma2(acc[o][3], wd, a1.y);
        }
    }
    #pragma unroll
    for (int o = 0; o < 8; o++) {
        float f[8];
        unpack2(acc[o][0], f[0], f[1]);
        unpack2(acc[o][1], f[2], f[3]);
        unpack2(acc[o][2], f[4], f[5]);
        unpack2(acc[o][3], f[6], f[7]);
        #pragma unroll
        for (int k = 0; k < 8; k++) f[k] = silu_f(f[k] * scale);
        *(float4*)&outb[(og * 8 + o) * 128 + e_lo] = make_float4(f[0], f[1], f[2], f[3]);
        *(float4*)&outb[(og * 8 + o) * 128 + e_hi] = make_float4(f[4], f[5], f[6], f[7]);
    }
}

// ---------------- kernel 4: radial chain, block-tiled GEMM over 128 edges ----------------
#define R_W1 0
#define R_W2 1024
#define R_W3 5120
#define R_BA 9216
#define R_BB 17408
#define R_SMEM_BYTES (25600 * 4)

__global__ __launch_bounds__(128) void k_radial(
    const float* __restrict__ pos, const int* __restrict__ batch,
    const int* __restrict__ src, const int* __restrict__ dst,
    const float* __restrict__ shifts, const float* __restrict__ cell,
    const float* __restrict__ fw1, const float* __restrict__ fw2,
    const float* __restrict__ fw3)
{
    extern __shared__ __align__(16) float sm[];
    int tid = threadIdx.x;
    for (int i = tid; i < 1024; i += 128) sm[R_W1 + i] = fw1[i];
    for (int i = tid; i < 4096; i += 128) sm[R_W2 + i] = fw2[i];
    for (int i = tid; i < 4096; i += 128) sm[R_W3 + i] = fw3[i];

    // P0: geometry + sh + rb -> bufA rows 0..15
    int e = blockIdx.x * 128 + tid;
    {
        int s = src[e], d = dst[e];
        float ex, ey, ez, r;
        edge_geom(pos, batch, shifts, cell, e, s, d, ex, ey, ez, r);

        float inv_r = __fdividef(1.0f, fmaxf(r, 1e-9f));
        float x = ex * inv_r, y = ey * inv_r, z = ez * inv_r;
        const float s3 = 1.7320508075688772f;
        const float s15 = 3.872983346207417f;
        const float s5 = 2.23606797749979f;
        *(float4*)&d_sh[e * 8 + 0] = make_float4(s3 * y, s3 * z, s3 * x, s15 * x * y);
        *(float4*)&d_sh[e * 8 + 4] = make_float4(s15 * y * z,
                                                 0.5f * s5 * (3.0f * z * z - 1.0f),
                                                 s15 * x * z,
                                                 0.5f * s15 * (x * x - y * y));
        const float step = 5.0f / 17.0f;
        const float inv_step = 17.0f / 5.0f;
        const float rb_scale = 4.0f / 1.12f;
        #pragma unroll
        for (int j = 0; j < 16; j++) {
            float c = step * (float)(j + 1);
            float t = (r - c) * inv_step;
            sm[R_BA + j * 128 + tid] = __expf(-t * t) * rb_scale;
        }
    }
    __syncthreads();

    const int eg = tid & 15, og = tid >> 4;

    gemm_layer<16>(sm + R_BA, sm + R_BB, sm + R_W1, 0.25f, eg, og);
    __syncthreads();
    gemm_layer<64>(sm + R_BB, sm + R_BA, sm + R_W2, 0.125f, eg, og);
    __syncthreads();
    gemm_layer<64>(sm + R_BA, sm + R_BB, sm + R_W3, 0.125f, eg, og);
    __syncthreads();

    // transpose out: bufB [c][edge] -> d_g3[e][c]
    #pragma unroll
    for (int k = 0; k < 16; k++) {
        float4 v = make_float4(sm[R_BB + (k * 4 + 0) * 128 + tid],
                               sm[R_BB + (k * 4 + 1) * 128 + tid],
                               sm[R_BB + (k * 4 + 2) * 128 + tid],
                               sm[R_BB + (k * 4 + 3) * 128 + tid]);
        *(float4*)&d_g3[e * 64 + k * 4] = v;
    }
}

// ---------------- kernel 5: scatter edges into CSR ----------------
__global__ void k_scatter(const int* __restrict__ edge_dst) {
    int e = blockIdx.x * 256 + threadIdx.x;
    if (e < N_EDGES) {
        int p = atomicAdd(&d_fill[edge_dst[e]], 1);
        d_csr[p] = e;
    }
}

// ---------------- kernel 6: factorized contraction, warp-per-node, per-l ----------------
template<int L>
__global__ __launch_bounds__(256, (L == 0) ? 3 : 2) void k_main(
    const int* __restrict__ src, float* __restrict__ out)
{
    constexpr int K   = (L == 0) ? 1 : (L == 1) ? 3 : 5;
    constexpr int OFF = (L == 0) ? 0 : (L == 1) ? 4 : 16;
    extern __shared__ float sM[];

    for (int idx = threadIdx.x; idx < 16384; idx += 256) {
        int cu = idx >> 5, vw = idx & 31;
        int v = vw >> 2, w = vw & 3;
        int pv = v ^ ((cu >> 4) & 7);
        sM[(cu << 5) + (pv << 2) + w] = d_Ml[L * 16384 + idx];
    }
    __syncthreads();

    const int wid = threadIdx.x >> 5;
    const int lane = threadIdx.x & 31;
    const u64 ONE2 = pack2(1.0f, 1.0f);

    for (int n = blockIdx.x * 8 + wid; n < N_NODES; n += gridDim.x * 8) {
        int beg = d_rowptr[n], end = d_rowptr[n + 1];
        int deg = end - beg;
        float* od = out + n * OUT_PER_NODE + OFF;
        if (deg == 0) {
            if (lane < 4 * K) od[lane] = 0.0f;
            continue;
        }

        u64 G[K][8];
        #pragma unroll
        for (int k = 0; k < K; k++)
            #pragma unroll
            for (int j = 0; j < 8; j++) G[k][j] = 0ULL;

        ulonglong2 p01, p23;
        float2 gpn;
        float4 shn = make_float4(0.f, 0.f, 0.f, 0.f);
        float shn2 = 0.f;
        {
            int e0 = d_csr[beg];
            int s0 = src[e0];
            const ulonglong2* ap = (const ulonglong2*)&d_Aip[s0 * 4];
            p01 = ap[0]; p23 = ap[1];
            gpn = *(const float2*)&d_g3[e0 * 64 + 2 * lane];
            if (L == 1) shn = *(const float4*)&d_sh[e0 * 8];
            if (L == 2) { shn2 = d_sh[e0 * 8 + 3]; shn = *(const float4*)&d_sh[e0 * 8 + 4]; }
        }
        for (int i = beg; i < end; i++) {
            u64 aa[4] = {p01.x, p01.y, p23.x, p23.y};
            float2 gp = gpn;
            float4 shc = shn;
            float shc2 = shn2;
            if (i + 1 < end) {
                int e2 = d_csr[i + 1];
                int s2 = src[e2];
                const ulonglong2* ap = (const ulonglong2*)&d_Aip[s2 * 4];
                p01 = ap[0]; p23 = ap[1];
                gpn = *(const float2*)&d_g3[e2 * 64 + 2 * lane];
                if (L == 1) shn = *(const float4*)&d_sh[e2 * 8];
                if (L == 2) { shn2 = d_sh[e2 * 8 + 3]; shn = *(const float4*)&d_sh[e2 * 8 + 4]; }
            }

            u64 g00 = pack2(gp.x, gp.x), g11 = pack2(gp.y, gp.y);
            u64 ff[8];
            #pragma unroll
            for (int j = 0; j < 4; j++) { ff[j] = 0ULL; ffma2(ff[j], g00, aa[j]); }
            #pragma unroll
            for (int j = 0; j < 4; j++) { ff[4 + j] = 0ULL; ffma2(ff[4 + j], g11, aa[j]); }

            if (L == 0) {
                #pragma unroll
                for (int j = 0; j < 8; j++) ffma2(G[0][j], ff[j], ONE2);
            } else if (L == 1) {
                float shv[3] = {shc.x, shc.y, shc.z};
                #pragma unroll
                for (int k = 0; k < 3; k++) {
                    u64 ss = pack2(shv[k], shv[k]);
                    #pragma unroll
                    for (int j = 0; j < 8; j++) ffma2(G[k][j], ff[j], ss);
                }
            } else {
                float shv[5] = {shc2, shc.x, shc.y, shc.z, shc.w};
                #pragma unroll
                for (int k = 0; k < 5; k++) {
                    u64 ss = pack2(shv[k], shv[k]);
                    #pragma unroll
                    for (int j = 0; j < 8; j++) ffma2(G[k][j], ff[j], ss);
                }
            }
        }

        float Ad[8];
        {
            const float4* Ai4 = (const float4*)&d_Ai[n * 8];
            float4 b0 = Ai4[0], b1 = Ai4[1];
            Ad[0] = b0.x; Ad[1] = b0.y; Ad[2] = b0.z; Ad[3] = b0.w;
            Ad[4] = b1.x; Ad[5] = b1.y; Ad[6] = b1.z; Ad[7] = b1.w;
        }
        u64 acc[K][2];
        #pragma unroll
        for (int k = 0; k < K; k++) { acc[k][0] = 0ULL; acc[k][1] = 0ULL; }

        #pragma unroll
        for (int j = 0; j < 8; j++) {
            u64 m00, m01, m10, m11;
            {
                int base0 = (lane * 16 + 2 * j) * 32;
                u64 a0 = 0ULL, a1 = 0ULL, b0 = 0ULL, b1 = 0ULL;
                #pragma unroll
                for (int v = 0; v < 8; v++) {
                    u64 ad = pack2(Ad[v], Ad[v]);
                    ulonglong2 mmA =
                        *(const ulonglong2*)&sM[base0 + ((v ^ (lane & 7)) << 2)];
                    ulonglong2 mmB =
                        *(const ulonglong2*)&sM[base0 + 32 + ((v ^ (lane & 7)) << 2)];
                    ffma2(a0, ad, mmA.x);
                    ffma2(a1, ad, mmA.y);
                    ffma2(b0, ad, mmB.x);
                    ffma2(b1, ad, mmB.y);
                }
                m00 = a0; m01 = a1; m10 = b0; m11 = b1;
            }
            #pragma unroll
            for (int k = 0; k < K; k++) {
                float ga, gb; unpack2(G[k][j], ga, gb);
                u64 gaa = pack2(ga, ga), gbb = pack2(gb, gb);
                ffma2(acc[k][0], gaa, m00);
                ffma2(acc[k][1], gaa, m01);
                ffma2(acc[k][0], gbb, m10);
                ffma2(acc[k][1], gbb, m11);
            }
        }

        #pragma unroll
        for (int off = 16; off; off >>= 1) {
            #pragma unroll
            for (int k = 0; k < K; k++) {
                u64 t0 = __shfl_xor_sync(0xffffffffu, acc[k][0], off);
                u64 t1 = __shfl_xor_sync(0xffffffffu, acc[k][1], off);
                ffma2(acc[k][0], t0, ONE2);
                ffma2(acc[k][1], t1, ONE2);
            }
        }

        if (lane == 0) {
            float sc = (1.0f / 64.0f) / (float)deg;
            #pragma unroll
            for (int k = 0; k < K; k++) {
                float W[4];
                unpack2(acc[k][0], W[0], W[1]);
                unpack2(acc[k][1], W[2], W[3]);
                #pragma unroll
                for (int w = 0; w < 4; w++) {
                    if (L == 0)      od[w] = W[w] * sc;
                    else if (L == 1) od[w * 3 + k] = W[w] * sc;
                    else             od[w * 5 + k] = W[w] * sc;
                }
            }
        }
    }
}

// ---------------- launch ----------------
extern "C" void kernel_launch(void* const* d_in, const int* in_sizes, int n_in,
                              void* d_out, int out_size) {
    const float* pos      = (const float*)d_in[0];
    const int*   A        = (const int*)d_in[1];
    const int*   batch    = (const int*)d_in[2];
    const int*   edge_src = (const int*)d_in[3];
    const int*   edge_dst = (const int*)d_in[4];
    const float* shifts   = (const float*)d_in[5];
    const float* cell     = (const float*)d_in[6];
    const float* emb      = (const float*)d_in[7];
    const float* fit_w1   = (const float*)d_in[8];
    const float* fit_b1   = (const float*)d_in[9];
    const float* fit_w2   = (const float*)d_in[10];
    const float* fit_b2   = (const float*)d_in[11];
    const float* fit_w3   = (const float*)d_in[12];
    const float* fit_b3   = (const float*)d_in[13];
    const float* fc_w1    = (const float*)d_in[14];
    const float* fc_w2    = (const float*)d_in[15];
    const float* fc_w3    = (const float*)d_in[16];
    const float* fc_w4    = (const float*)d_in[17];
    float* out = (float*)d_out;

    cudaFuncSetAttribute(k_radial, cudaFuncAttributeMaxDynamicSharedMemorySize,
                         R_SMEM_BYTES);
    cudaFuncSetAttribute(k_main<0>, cudaFuncAttributeMaxDynamicSharedMemorySize, 65536);
    cudaFuncSetAttribute(k_main<1>, cudaFuncAttributeMaxDynamicSharedMemorySize, 65536);
    cudaFuncSetAttribute(k_main<2>, cudaFuncAttributeMaxDynamicSharedMemorySize, 65536);

    k_zero<<<(N_NODES + 255) / 256, 256>>>();
    k_prepcount<<<NODE_BLOCKS + PERM_BLOCKS + (N_EDGES / 256), 256>>>(
        emb, fit_w1, fit_b1, fit_w2, fit_b2, fit_w3, fit_b3, A, fc_w4, edge_dst);
    k_scan<<<1, 1024>>>();
    k_radial<<<N_EDGES / 128, 128, R_SMEM_BYTES>>>(pos, batch, edge_src, edge_dst,
                                                   shifts, cell, fc_w1, fc_w2, fc_w3);
    k_scatter<<<N_EDGES / 256, 256>>>(edge_dst);
    k_main<0><<<444, 256, 65536>>>(edge_src, out);
    k_main<1><<<296, 256, 65536>>>(edge_src, out);
    k_main<2><<<296, 256, 65536>>>(edge_src, out);
}